// round 14
// baseline (speedup 1.0000x reference)
#include <cuda_runtime.h>
#include <cuda_fp16.h>
#include <cstdint>

#define NN  50000
#define NE  800000
#define NN_PAD 50048              // 391 * 128
#define FIN 256
#define H1  4
#define D1  64
#define C2  47

// ---------------- scratch (device globals; no allocation allowed) ----------------
__device__ __align__(16) __half g_fs1[(size_t)NN * FIN];   // layer-1 features, fp16
__device__ __align__(16) __half g_fs2h[(size_t)NN * 64];   // layer-2 features, fp16 padded
__device__ __align__(16) float g_el1[NN * H1];
__device__ __align__(16) float g_er1[NN * H1];
__device__ __align__(16) float g_el2[NN];
__device__ __align__(16) float g_er2[NN];
__device__ __align__(16) int   g_rowptr[NN + 1];
// fp16 transposed weights: W1^T [256,256], W2^T padded [64,256]
__device__ __align__(16) __half g_w1h[256 * 256];
__device__ __align__(16) __half g_w2h[64 * 256];

// ================= warp-level MMA helpers (arch-agnostic PTX, sm_80+) =================
__device__ __forceinline__ uint32_t smem_to_u32(const void* p) {
    uint32_t a;
    asm("{ .reg .u64 t; cvta.to.shared.u64 t, %1; cvt.u32.u64 %0, t; }" : "=r"(a) : "l"(p));
    return a;
}
__device__ __forceinline__ void ldsm_x4(uint32_t addr, uint32_t r[4]) {
    asm volatile("ldmatrix.sync.aligned.m8n8.x4.shared.b16 {%0,%1,%2,%3}, [%4];"
                 : "=r"(r[0]), "=r"(r[1]), "=r"(r[2]), "=r"(r[3]) : "r"(addr));
}
__device__ __forceinline__ void ldsm_x2(uint32_t addr, uint32_t r[2]) {
    asm volatile("ldmatrix.sync.aligned.m8n8.x2.shared.b16 {%0,%1}, [%2];"
                 : "=r"(r[0]), "=r"(r[1]) : "r"(addr));
}
__device__ __forceinline__ void mma_f16(float c[4], const uint32_t a[4], const uint32_t b[2]) {
    asm volatile("mma.sync.aligned.m16n8k16.row.col.f32.f16.f16.f32 "
                 "{%0,%1,%2,%3}, {%4,%5,%6,%7}, {%8,%9}, {%0,%1,%2,%3};"
                 : "+f"(c[0]), "+f"(c[1]), "+f"(c[2]), "+f"(c[3])
                 : "r"(a[0]), "r"(a[1]), "r"(a[2]), "r"(a[3]), "r"(b[0]), "r"(b[1]));
}
// ---- cp.async (sm_80+): 16B global->shared, src_bytes<16 zero-fills ----
__device__ __forceinline__ void cp_async16(uint32_t saddr, const void* gaddr, int src_bytes) {
    asm volatile("cp.async.cg.shared.global [%0], [%1], 16, %2;"
                 :: "r"(saddr), "l"(gaddr), "r"(src_bytes) : "memory");
}
#define CP_COMMIT() asm volatile("cp.async.commit_group;" ::: "memory")
#define CP_WAIT(n)  asm volatile("cp.async.wait_group %0;" :: "n"(n) : "memory")

// ================= prep: coalesced W transposes (smem tiles) + CSR rowptr =================
#define PREP_ROWPTR_BLOCKS ((NN + 1 + 255) / 256)
__global__ void prep_kernel(const float* __restrict__ W1, const float* __restrict__ W2,
                            const int* __restrict__ dst)
{
    const int b = blockIdx.x;
    const int tid = threadIdx.x;
    if (b < 20) {
        __shared__ float ts[64][65];
        if (b < 16) {
            const int k0 = (b >> 2) * 64, n0 = (b & 3) * 64;
#pragma unroll
            for (int i = 0; i < 16; ++i) {
                int e = tid + i * 256;
                int r = e >> 6, c = e & 63;
                ts[r][c] = W1[(size_t)(k0 + r) * 256 + n0 + c];
            }
            __syncthreads();
#pragma unroll
            for (int i = 0; i < 16; ++i) {
                int e = tid + i * 256;
                int r2 = e >> 6, c2 = e & 63;
                g_w1h[(size_t)(n0 + r2) * 256 + k0 + c2] = __float2half_rn(ts[c2][r2]);
            }
        } else {
            const int k0 = (b - 16) * 64;
#pragma unroll
            for (int i = 0; i < 16; ++i) {
                int e = tid + i * 256;
                int r = e >> 6, c = e & 63;
                ts[r][c] = (c < C2) ? W2[(size_t)(k0 + r) * C2 + c] : 0.f;
            }
            __syncthreads();
#pragma unroll
            for (int i = 0; i < 16; ++i) {
                int e = tid + i * 256;
                int r2 = e >> 6, c2 = e & 63;
                g_w2h[(size_t)r2 * 256 + k0 + c2] = __float2half_rn(ts[c2][r2]);
            }
        }
    } else {
        int n = (b - 20) * 256 + tid;
        if (n > NN) return;
        int lo = 0, hi = NE;
        while (lo < hi) {
            int mid = (lo + hi) >> 1;
            if (dst[mid] < n) lo = mid + 1; else hi = mid;
        }
        g_rowptr[n] = lo;
    }
}

// ================= shared tiling constants =================
#define LDT 264                       // padded row stride in 16-bit elems (528 B)
#define OFF_A 0
#define OFF_B (128 * LDT * 2)         // 67584
#define GEMM_SMEM (OFF_B + 64 * LDT * 2)   // 101376 B dynamic -> 2 CTAs/SM

__device__ __forceinline__ void load_A_fp16(const float* __restrict__ src, int row0,
                                            __half* Aa, int tid)
{
#pragma unroll
    for (int i = 0; i < 16; ++i) {
        int idx = tid + i * 512;
        int r = idx >> 6, q = (idx & 63) * 4;
        int gr = row0 + r;
        float4 v = make_float4(0.f, 0.f, 0.f, 0.f);
        if (gr < NN) v = *reinterpret_cast<const float4*>(src + (size_t)gr * 256 + q);
        __half2 p0 = __floats2half2_rn(v.x, v.y);
        __half2 p1 = __floats2half2_rn(v.z, v.w);
        *reinterpret_cast<uint2*>(Aa + r * LDT + q) =
            make_uint2(*reinterpret_cast<uint32_t*>(&p0), *reinterpret_cast<uint32_t*>(&p1));
    }
}
__device__ __forceinline__ void cp_B_half(const __half* __restrict__ src, int rowoff,
                                          uint32_t sbB, int tid)
{
#pragma unroll
    for (int i = 0; i < 4; ++i) {
        int idx = tid + i * 512;
        int r = idx >> 5, c8 = (idx & 31) * 8;
        cp_async16(sbB + (uint32_t)(r * LDT + c8) * 2,
                   src + (size_t)(rowoff + r) * 256 + c8, 16);
    }
}

// warp MMA over ks in [ks0, ks1), accumulating into c
__device__ __forceinline__ void mma_krange_f16(uint32_t sb, int m0, int n0,
                                               int ks0, int ks1, float c[4][4])
{
    const int lane = threadIdx.x & 31;
    uint32_t aA = sb + OFF_A + (uint32_t)((m0 + (lane & 15)) * LDT + ((lane >> 4) & 1) * 8) * 2 + ks0 * 32;
    uint32_t aB = sb + OFF_B + (uint32_t)((n0 + (lane & 7)) * LDT + ((lane >> 3) & 1) * 8) * 2 + ks0 * 32;
    for (int ks = ks0; ks < ks1; ++ks) {
        uint32_t fA[4];
        ldsm_x4(aA, fA);
#pragma unroll
        for (int g = 0; g < 4; ++g) {
            uint32_t b[2];
            ldsm_x2(aB + g * 8 * LDT * 2, b);
            mma_f16(c[g], fA, b);
        }
        aA += 32; aB += 32;
    }
}

// ================= GEMM1 (x @ W1) + el1/er1, 4 head-tiles per CTA; fs1 stored fp16 =========
__global__ void __launch_bounds__(512, 2) gemm1_mma_kernel(const float* __restrict__ x,
                                                           const float* __restrict__ al1,
                                                           const float* __restrict__ ar1)
{
    extern __shared__ __align__(16) char dsm[];
    __shared__ float als[256], ars[256];
    __shared__ float elp[2][128], erp[2][128];

    const uint32_t sb = smem_to_u32(dsm);
    const int tid  = threadIdx.x;
    const int lane = tid & 31;
    const int wid  = tid >> 5;
    const int wm = wid >> 1, wn = wid & 1;
    const int m0 = wm * 16, n0 = wn * 32;
    const int row0 = blockIdx.x * 128;

    __half* Aa = reinterpret_cast<__half*>(dsm + OFF_A);

    cp_B_half(g_w1h, 0, sb + OFF_B, tid);
    CP_COMMIT();
    load_A_fp16(x, row0, Aa, tid);
    if (tid < 256) { als[tid] = al1[tid]; ars[tid] = ar1[tid]; }

#pragma unroll 1
    for (int ct = 0; ct < 4; ++ct) {
        const int col0 = ct * 64;
        CP_WAIT(0);
        __syncthreads();

        float c[4][4];
#pragma unroll
        for (int g = 0; g < 4; ++g)
#pragma unroll
            for (int q = 0; q < 4; ++q) c[g][q] = 0.f;
        mma_krange_f16(sb, m0, n0, 0, 16, c);

        __syncthreads();
        if (ct < 3) {
            cp_B_half(g_w1h, col0 + 64, sb + OFF_B, tid);
            CP_COMMIT();
        }

        const int r0 = row0 + m0 + (lane >> 2);
        const int cbl = n0 + 2 * (lane & 3);
        float pel0 = 0.f, per0 = 0.f, pel8 = 0.f, per8 = 0.f;
#pragma unroll
        for (int g = 0; g < 4; ++g) {
            float a0 = als[col0 + cbl + g * 8], a1 = als[col0 + cbl + g * 8 + 1];
            float b0 = ars[col0 + cbl + g * 8], b1 = ars[col0 + cbl + g * 8 + 1];
            pel0 += c[g][0] * a0 + c[g][1] * a1;
            per0 += c[g][0] * b0 + c[g][1] * b1;
            pel8 += c[g][2] * a0 + c[g][3] * a1;
            per8 += c[g][2] * b0 + c[g][3] * b1;
            if (r0 < NN)
                *reinterpret_cast<__half2*>(g_fs1 + (size_t)r0 * 256 + col0 + cbl + g * 8) =
                    __floats2half2_rn(c[g][0], c[g][1]);
            if (r0 + 8 < NN)
                *reinterpret_cast<__half2*>(g_fs1 + (size_t)(r0 + 8) * 256 + col0 + cbl + g * 8) =
                    __floats2half2_rn(c[g][2], c[g][3]);
        }
        pel0 += __shfl_xor_sync(0xffffffffu, pel0, 1); pel0 += __shfl_xor_sync(0xffffffffu, pel0, 2);
        per0 += __shfl_xor_sync(0xffffffffu, per0, 1); per0 += __shfl_xor_sync(0xffffffffu, per0, 2);
        pel8 += __shfl_xor_sync(0xffffffffu, pel8, 1); pel8 += __shfl_xor_sync(0xffffffffu, pel8, 2);
        per8 += __shfl_xor_sync(0xffffffffu, per8, 1); per8 += __shfl_xor_sync(0xffffffffu, per8, 2);
        if ((lane & 3) == 0) {
            int rr = m0 + (lane >> 2);
            elp[wn][rr] = pel0; elp[wn][rr + 8] = pel8;
            erp[wn][rr] = per0; erp[wn][rr + 8] = per8;
        }
        __syncthreads();
        if (tid < 128) {
            int row = row0 + tid;
            if (row < NN) {
                g_el1[row * 4 + ct] = elp[0][tid] + elp[1][tid];
                g_er1[row * 4 + ct] = erp[0][tid] + erp[1][tid];
            }
        }
    }
}

// ================= FUSED: agg1 (segment softmax over fs1) -> smem A tile -> GEMM2 ==========
// Block = 128 nodes (one MMA M-tile). Warp w aggregates nodes {nb+w, nb+w+16, ...} (8 each),
// writing h2 rows straight into the smem A tile. Weight staging aliases the B region
// (B = W2 is loaded only after the agg phase). Then fp16 MMA + el2/er2 epilogue.
__global__ void __launch_bounds__(512, 2) agg1_gemm2_kernel(const int* __restrict__ src,
                                                            const float* __restrict__ b1,
                                                            const float* __restrict__ al2,
                                                            const float* __restrict__ ar2)
{
    extern __shared__ __align__(16) char dsm[];
    __shared__ float als[64], ars[64];
    __shared__ float elp[2][128], erp[2][128];

    const uint32_t sb = smem_to_u32(dsm);
    const int tid  = threadIdx.x;
    const int lane = tid & 31;
    const int wid  = tid >> 5;               // 0..15
    const int nb   = blockIdx.x * 128;

    __half* Aa = reinterpret_cast<__half*>(dsm + OFF_A);
    // per-warp staging inside the (not-yet-loaded) B region: 768 B/warp
    __half2* stw = reinterpret_cast<__half2*>(dsm + OFF_B + wid * 768);
    int*     sts = reinterpret_cast<int*>(dsm + OFF_B + wid * 768 + 512);

    if (tid < 64) {
        als[tid] = (tid < C2) ? al2[tid] : 0.f;
        ars[tid] = (tid < C2) ? ar2[tid] : 0.f;
    }

    const int h = lane >> 3;
    const float4 bb0 = *reinterpret_cast<const float4*>(b1 + lane * 8);
    const float4 bb1 = *reinterpret_cast<const float4*>(b1 + lane * 8 + 4);

    // ---- agg phase: 8 nodes per warp ----
#pragma unroll 1
    for (int i = 0; i < 8; ++i) {
        const int r = wid + i * 16;           // tile row
        const int n = nb + r;
        uint4* orow = reinterpret_cast<uint4*>(Aa + r * LDT + lane * 8);
        if (n >= NN) { *orow = make_uint4(0u, 0u, 0u, 0u); continue; }

        const int s = g_rowptr[n];
        const int e = g_rowptr[n + 1];
        const float4 er = *reinterpret_cast<const float4*>(g_er1 + n * 4);

        float2 acc2[4];
#pragma unroll
        for (int q = 0; q < 4; ++q) acc2[q] = make_float2(0.f, 0.f);
        float den = 0.f;

        for (int base = s; base < e; base += 32) {
            int cnt = min(32, e - base);
            float4 wv = make_float4(0.f, 0.f, 0.f, 0.f);
            int sj = 0;
            if (lane < cnt) {
                sj = src[base + lane];
                float4 el = *reinterpret_cast<const float4*>(g_el1 + sj * 4);
                float v;
                v = el.x + er.x; v = v > 0.f ? v : 0.2f * v; wv.x = __expf(v);
                v = el.y + er.y; v = v > 0.f ? v : 0.2f * v; wv.y = __expf(v);
                v = el.z + er.z; v = v > 0.f ? v : 0.2f * v; wv.z = __expf(v);
                v = el.w + er.w; v = v > 0.f ? v : 0.2f * v; wv.w = __expf(v);
            }
            sts[lane] = sj;
            __half2 wh0 = __float2half2_rn(wv.x);
            __half2 wh1 = __float2half2_rn(wv.y);
            __half2 wh2 = __float2half2_rn(wv.z);
            __half2 wh3 = __float2half2_rn(wv.w);
            uint4 packed;
            packed.x = *reinterpret_cast<uint32_t*>(&wh0);
            packed.y = *reinterpret_cast<uint32_t*>(&wh1);
            packed.z = *reinterpret_cast<uint32_t*>(&wh2);
            packed.w = *reinterpret_cast<uint32_t*>(&wh3);
            *reinterpret_cast<uint4*>(&stw[lane * 4]) = packed;
            __syncwarp();

            const int cnt4 = (cnt + 3) & ~3;
            uint4   fc[4];
            __half2 wc[4];
#pragma unroll
            for (int t = 0; t < 4; ++t) {
                wc[t] = stw[t * 4 + h];
                fc[t] = *reinterpret_cast<const uint4*>(
                    g_fs1 + (size_t)sts[t] * 256 + lane * 8);
            }
            int j0 = 0;
#pragma unroll 1
            for (; j0 + 4 < cnt4; j0 += 4) {
                uint4   fn[4];
                __half2 wn[4];
#pragma unroll
                for (int t = 0; t < 4; ++t) {
                    wn[t] = stw[(j0 + 4 + t) * 4 + h];
                    fn[t] = *reinterpret_cast<const uint4*>(
                        g_fs1 + (size_t)sts[j0 + 4 + t] * 256 + lane * 8);
                }
                __half2 hacc[4];
                {
                    const __half2* hp = reinterpret_cast<const __half2*>(&fc[0]);
                    den += __low2float(wc[0]);
#pragma unroll
                    for (int q = 0; q < 4; ++q) hacc[q] = __hmul2(wc[0], hp[q]);
                }
#pragma unroll
                for (int t = 1; t < 4; ++t) {
                    const __half2* hp = reinterpret_cast<const __half2*>(&fc[t]);
                    den += __low2float(wc[t]);
#pragma unroll
                    for (int q = 0; q < 4; ++q) hacc[q] = __hfma2(wc[t], hp[q], hacc[q]);
                }
#pragma unroll
                for (int q = 0; q < 4; ++q) {
                    float2 fa = __half22float2(hacc[q]);
                    acc2[q].x += fa.x; acc2[q].y += fa.y;
                }
#pragma unroll
                for (int t = 0; t < 4; ++t) { fc[t] = fn[t]; wc[t] = wn[t]; }
            }
            {
                __half2 hacc[4];
                {
                    const __half2* hp = reinterpret_cast<const __half2*>(&fc[0]);
                    den += __low2float(wc[0]);
#pragma unroll
                    for (int q = 0; q < 4; ++q) hacc[q] = __hmul2(wc[0], hp[q]);
                }
#pragma unroll
                for (int t = 1; t < 4; ++t) {
                    const __half2* hp = reinterpret_cast<const __half2*>(&fc[t]);
                    den += __low2float(wc[t]);
#pragma unroll
                    for (int q = 0; q < 4; ++q) hacc[q] = __hfma2(wc[t], hp[q], hacc[q]);
                }
#pragma unroll
                for (int q = 0; q < 4; ++q) {
                    float2 fa = __half22float2(hacc[q]);
                    acc2[q].x += fa.x; acc2[q].y += fa.y;
                }
            }
            __syncwarp();
        }

        float rden = (e > s) ? 1.f / den : 0.f;
        __half2 o[4];
        o[0] = __floats2half2_rn(fmaxf(acc2[0].x * rden + bb0.x, 0.f), fmaxf(acc2[0].y * rden + bb0.y, 0.f));
        o[1] = __floats2half2_rn(fmaxf(acc2[1].x * rden + bb0.z, 0.f), fmaxf(acc2[1].y * rden + bb0.w, 0.f));
        o[2] = __floats2half2_rn(fmaxf(acc2[2].x * rden + bb1.x, 0.f), fmaxf(acc2[2].y * rden + bb1.y, 0.f));
        o[3] = __floats2half2_rn(fmaxf(acc2[3].x * rden + bb1.z, 0.f), fmaxf(acc2[3].y * rden + bb1.w, 0.f));
        *orow = *reinterpret_cast<uint4*>(o);
    }

    __syncthreads();                      // all h2 rows in smem; staging dead
    cp_B_half(g_w2h, 0, sb + OFF_B, tid); // W2 tile (L2-hot)
    CP_COMMIT();
    CP_WAIT(0);
    __syncthreads();

    // ---- MMA phase (identical to gemm2) ----
    const int wm = wid >> 1, wn = wid & 1;
    const int m0 = wm * 16, n0 = wn * 32;

    float c[4][4];
#pragma unroll
    for (int g = 0; g < 4; ++g)
#pragma unroll
        for (int q = 0; q < 4; ++q) c[g][q] = 0.f;
    mma_krange_f16(sb, m0, n0, 0, 16, c);

    const int r0 = nb + m0 + (lane >> 2);
    const int cbl = n0 + 2 * (lane & 3);
    float pel0 = 0.f, per0 = 0.f, pel8 = 0.f, per8 = 0.f;
#pragma unroll
    for (int g = 0; g < 4; ++g) {
        int cc = cbl + g * 8;
        float a0 = als[cc], a1 = als[cc + 1];
        float b0 = ars[cc], b1 = ars[cc + 1];
        pel0 += c[g][0] * a0 + c[g][1] * a1;
        per0 += c[g][0] * b0 + c[g][1] * b1;
        pel8 += c[g][2] * a0 + c[g][3] * a1;
        per8 += c[g][2] * b0 + c[g][3] * b1;
        if (r0 < NN)
            *reinterpret_cast<__half2*>(g_fs2h + (size_t)r0 * 64 + cc) =
                __floats2half2_rn(c[g][0], c[g][1]);
        if (r0 + 8 < NN)
            *reinterpret_cast<__half2*>(g_fs2h + (size_t)(r0 + 8) * 64 + cc) =
                __floats2half2_rn(c[g][2], c[g][3]);
    }
    pel0 += __shfl_xor_sync(0xffffffffu, pel0, 1); pel0 += __shfl_xor_sync(0xffffffffu, pel0, 2);
    per0 += __shfl_xor_sync(0xffffffffu, per0, 1); per0 += __shfl_xor_sync(0xffffffffu, per0, 2);
    pel8 += __shfl_xor_sync(0xffffffffu, pel8, 1); pel8 += __shfl_xor_sync(0xffffffffu, pel8, 2);
    per8 += __shfl_xor_sync(0xffffffffu, per8, 1); per8 += __shfl_xor_sync(0xffffffffu, per8, 2);
    if ((lane & 3) == 0) {
        int rr = m0 + (lane >> 2);
        elp[wn][rr] = pel0; elp[wn][rr + 8] = pel8;
        erp[wn][rr] = per0; erp[wn][rr + 8] = per8;
    }
    __syncthreads();
    if (tid < 128) {
        int row = nb + tid;
        if (row < NN) {
            g_el2[row] = elp[0][tid] + elp[1][tid];
            g_er2[row] = erp[0][tid] + erp[1][tid];
        }
    }
}

// ---------------- layer-2 aggregation: WARP per node, software-pipelined gather ----------
__global__ void __launch_bounds__(128, 12) agg2_kernel(const int* __restrict__ src,
                                                       const float* __restrict__ b2,
                                                       float* __restrict__ out)
{
    __shared__ __half2 smwh[4][32];
    __shared__ int     smsrc[4][32];

    const int w    = threadIdx.x >> 5;
    const int lane = threadIdx.x & 31;
    const int n    = blockIdx.x * 4 + w;
    const int s = g_rowptr[n];
    const int e = g_rowptr[n + 1];
    const float ern = g_er2[n];

    float2 acc = make_float2(0.f, 0.f);
    float den = 0.f;
    for (int base = s; base < e; base += 32) {
        int cnt = min(32, e - base);
        float wv = 0.f; int sj = 0;
        if (lane < cnt) {
            sj = src[base + lane];
            float v = g_el2[sj] + ern;
            v = v > 0.f ? v : 0.2f * v;
            wv = __expf(v);
        }
        smsrc[w][lane] = sj;
        smwh[w][lane] = __float2half2_rn(wv);
        __syncwarp();

        const int cnt4 = (cnt + 3) & ~3;
        __half2 fc[4], wc[4];
#pragma unroll
        for (int t = 0; t < 4; ++t) {
            wc[t] = smwh[w][t];
            fc[t] = *reinterpret_cast<const __half2*>(
                g_fs2h + (size_t)smsrc[w][t] * 64 + lane * 2);
        }
        int j0 = 0;
#pragma unroll 1
        for (; j0 + 4 < cnt4; j0 += 4) {
            __half2 fn[4], wn[4];
#pragma unroll
            for (int t = 0; t < 4; ++t) {
                wn[t] = smwh[w][j0 + 4 + t];
                fn[t] = *reinterpret_cast<const __half2*>(
                    g_fs2h + (size_t)smsrc[w][j0 + 4 + t] * 64 + lane * 2);
            }
            __half2 hacc = __hmul2(wc[0], fc[0]);
            den += __low2float(wc[0]);
#pragma unroll
            for (int t = 1; t < 4; ++t) {
                den += __low2float(wc[t]);
                hacc = __hfma2(wc[t], fc[t], hacc);
            }
            float2 fa = __half22float2(hacc);
            acc.x += fa.x; acc.y += fa.y;
#pragma unroll
            for (int t = 0; t < 4; ++t) { fc[t] = fn[t]; wc[t] = wn[t]; }
        }
        {
            __half2 hacc = __hmul2(wc[0], fc[0]);
            den += __low2float(wc[0]);
#pragma unroll
            for (int t = 1; t < 4; ++t) {
                den += __low2float(wc[t]);
                hacc = __hfma2(wc[t], fc[t], hacc);
            }
            float2 fa = __half22float2(hacc);
            acc.x += fa.x; acc.y += fa.y;
        }
        __syncwarp();
    }

    float rden = (e > s) ? 1.f / den : 0.f;
    float* orow = out + (size_t)n * C2;
    int cc = lane * 2;
    if (cc < C2)     orow[cc]     = acc.x * rden + b2[cc];
    if (cc + 1 < C2) orow[cc + 1] = acc.y * rden + b2[cc + 1];
}

// ---------------- launch ----------------
extern "C" void kernel_launch(void* const* d_in, const int* in_sizes, int n_in,
                              void* d_out, int out_size)
{
    const float* x   = (const float*)d_in[0];
    const float* W1  = (const float*)d_in[1];
    const float* al1 = (const float*)d_in[2];
    const float* ar1 = (const float*)d_in[3];
    const float* b1  = (const float*)d_in[4];
    const float* W2  = (const float*)d_in[5];
    const float* al2 = (const float*)d_in[6];
    const float* ar2 = (const float*)d_in[7];
    const float* b2  = (const float*)d_in[8];
    const int*   src = (const int*)d_in[9];
    const int*   dst = (const int*)d_in[10];
    float* out = (float*)d_out;

    (void)in_sizes; (void)n_in; (void)out_size;

    cudaFuncSetAttribute(gemm1_mma_kernel,
                         cudaFuncAttributeMaxDynamicSharedMemorySize, GEMM_SMEM);
    cudaFuncSetAttribute(agg1_gemm2_kernel,
                         cudaFuncAttributeMaxDynamicSharedMemorySize, GEMM_SMEM);

    prep_kernel<<<20 + PREP_ROWPTR_BLOCKS, 256>>>(W1, W2, dst);

    // Layer 1 GEMM + logits
    gemm1_mma_kernel<<<NN_PAD / 128, 512, GEMM_SMEM>>>(x, al1, ar1);

    // Fused: layer-1 aggregation -> smem -> layer-2 GEMM + logits
    agg1_gemm2_kernel<<<NN_PAD / 128, 512, GEMM_SMEM>>>(src, b1, al2, ar2);

    // Layer-2 aggregation -> output
    agg2_kernel<<<NN / 4, 128>>>(src, b2, out);
}

// round 15
// speedup vs baseline: 1.0470x; 1.0470x over previous
#include <cuda_runtime.h>
#include <cuda_fp16.h>
#include <cstdint>

#define NN  50000
#define NE  800000
#define NN_PAD 50048              // 391 * 128
#define FIN 256
#define H1  4
#define D1  64
#define C2  47

// ---------------- scratch (device globals; no allocation allowed) ----------------
__device__ __align__(16) __half g_fs1[(size_t)NN * FIN];   // layer-1 features, fp16
__device__ __align__(16) __half g_h2 [(size_t)NN * FIN];   // relu(layer-1 out), fp16
__device__ __align__(16) __half g_fs2h[(size_t)NN * 64];   // layer-2 features, fp16 padded
__device__ __align__(16) float g_el1[NN * H1];
__device__ __align__(16) float g_er1[NN * H1];
__device__ __align__(16) float g_el2[NN];
__device__ __align__(16) float g_er2[NN];
__device__ __align__(16) int   g_rowptr[NN + 1];
// fp16 transposed weights: W1^T [256,256], W2^T padded [64,256]
__device__ __align__(16) __half g_w1h[256 * 256];
__device__ __align__(16) __half g_w2h[64 * 256];

// ================= warp-level MMA helpers (arch-agnostic PTX, sm_80+) =================
__device__ __forceinline__ uint32_t smem_to_u32(const void* p) {
    uint32_t a;
    asm("{ .reg .u64 t; cvta.to.shared.u64 t, %1; cvt.u32.u64 %0, t; }" : "=r"(a) : "l"(p));
    return a;
}
__device__ __forceinline__ void ldsm_x4(uint32_t addr, uint32_t r[4]) {
    asm volatile("ldmatrix.sync.aligned.m8n8.x4.shared.b16 {%0,%1,%2,%3}, [%4];"
                 : "=r"(r[0]), "=r"(r[1]), "=r"(r[2]), "=r"(r[3]) : "r"(addr));
}
__device__ __forceinline__ void ldsm_x2(uint32_t addr, uint32_t r[2]) {
    asm volatile("ldmatrix.sync.aligned.m8n8.x2.shared.b16 {%0,%1}, [%2];"
                 : "=r"(r[0]), "=r"(r[1]) : "r"(addr));
}
__device__ __forceinline__ void mma_f16(float c[4], const uint32_t a[4], const uint32_t b[2]) {
    asm volatile("mma.sync.aligned.m16n8k16.row.col.f32.f16.f16.f32 "
                 "{%0,%1,%2,%3}, {%4,%5,%6,%7}, {%8,%9}, {%0,%1,%2,%3};"
                 : "+f"(c[0]), "+f"(c[1]), "+f"(c[2]), "+f"(c[3])
                 : "r"(a[0]), "r"(a[1]), "r"(a[2]), "r"(a[3]), "r"(b[0]), "r"(b[1]));
}
// ---- cp.async (sm_80+): 16B global->shared, src_bytes<16 zero-fills ----
__device__ __forceinline__ void cp_async16(uint32_t saddr, const void* gaddr, int src_bytes) {
    asm volatile("cp.async.cg.shared.global [%0], [%1], 16, %2;"
                 :: "r"(saddr), "l"(gaddr), "r"(src_bytes) : "memory");
}
#define CP_COMMIT() asm volatile("cp.async.commit_group;" ::: "memory")
#define CP_WAIT(n)  asm volatile("cp.async.wait_group %0;" :: "n"(n) : "memory")

// ================= prep: coalesced W transposes (smem tiles) + CSR rowptr =================
#define PREP_ROWPTR_BLOCKS ((NN + 1 + 255) / 256)
__global__ void prep_kernel(const float* __restrict__ W1, const float* __restrict__ W2,
                            const int* __restrict__ dst)
{
    const int b = blockIdx.x;
    const int tid = threadIdx.x;
    if (b < 20) {
        __shared__ float ts[64][65];
        if (b < 16) {
            const int k0 = (b >> 2) * 64, n0 = (b & 3) * 64;
#pragma unroll
            for (int i = 0; i < 16; ++i) {
                int e = tid + i * 256;
                int r = e >> 6, c = e & 63;
                ts[r][c] = W1[(size_t)(k0 + r) * 256 + n0 + c];
            }
            __syncthreads();
#pragma unroll
            for (int i = 0; i < 16; ++i) {
                int e = tid + i * 256;
                int r2 = e >> 6, c2 = e & 63;
                g_w1h[(size_t)(n0 + r2) * 256 + k0 + c2] = __float2half_rn(ts[c2][r2]);
            }
        } else {
            const int k0 = (b - 16) * 64;
#pragma unroll
            for (int i = 0; i < 16; ++i) {
                int e = tid + i * 256;
                int r = e >> 6, c = e & 63;
                ts[r][c] = (c < C2) ? W2[(size_t)(k0 + r) * C2 + c] : 0.f;
            }
            __syncthreads();
#pragma unroll
            for (int i = 0; i < 16; ++i) {
                int e = tid + i * 256;
                int r2 = e >> 6, c2 = e & 63;
                g_w2h[(size_t)r2 * 256 + k0 + c2] = __float2half_rn(ts[c2][r2]);
            }
        }
    } else {
        int n = (b - 20) * 256 + tid;
        if (n > NN) return;
        int lo = 0, hi = NE;
        while (lo < hi) {
            int mid = (lo + hi) >> 1;
            if (dst[mid] < n) lo = mid + 1; else hi = mid;
        }
        g_rowptr[n] = lo;
    }
}

// ================= fused GEMM + attention-logit kernels (single fp16 term) =============
#define LDT 264                       // padded row stride in 16-bit elems (528 B)
#define OFF_A 0
#define OFF_B (128 * LDT * 2)         // 67584
#define GEMM_SMEM (OFF_B + 64 * LDT * 2)   // 101376 B dynamic -> 2 CTAs/SM

__device__ __forceinline__ void load_A_fp16(const float* __restrict__ src, int row0,
                                            __half* Aa, int tid)
{
#pragma unroll
    for (int i = 0; i < 16; ++i) {
        int idx = tid + i * 512;
        int r = idx >> 6, q = (idx & 63) * 4;
        int gr = row0 + r;
        float4 v = make_float4(0.f, 0.f, 0.f, 0.f);
        if (gr < NN) v = *reinterpret_cast<const float4*>(src + (size_t)gr * 256 + q);
        __half2 p0 = __floats2half2_rn(v.x, v.y);
        __half2 p1 = __floats2half2_rn(v.z, v.w);
        *reinterpret_cast<uint2*>(Aa + r * LDT + q) =
            make_uint2(*reinterpret_cast<uint32_t*>(&p0), *reinterpret_cast<uint32_t*>(&p1));
    }
}
__device__ __forceinline__ void cp_A_half_chunk(const __half* __restrict__ src, int row0,
                                                uint32_t sbA, int tid, int chunk)
{
#pragma unroll
    for (int i = 0; i < 4; ++i) {
        int idx = tid + i * 512;
        int r = idx >> 4, c8 = (idx & 15) * 8 + chunk * 128;
        int gr = row0 + r;
        cp_async16(sbA + (uint32_t)(r * LDT + c8) * 2,
                   src + (size_t)gr * 256 + c8, (gr < NN) ? 16 : 0);
    }
}
__device__ __forceinline__ void cp_B_half_chunk(const __half* __restrict__ src, int rowoff,
                                                uint32_t sbB, int tid, int chunk)
{
#pragma unroll
    for (int i = 0; i < 2; ++i) {
        int idx = tid + i * 512;
        int r = idx >> 4, c8 = (idx & 15) * 8 + chunk * 128;
        cp_async16(sbB + (uint32_t)(r * LDT + c8) * 2,
                   src + (size_t)(rowoff + r) * 256 + c8, 16);
    }
}
__device__ __forceinline__ void cp_B_half(const __half* __restrict__ src, int rowoff,
                                          uint32_t sbB, int tid)
{
#pragma unroll
    for (int i = 0; i < 4; ++i) {
        int idx = tid + i * 512;
        int r = idx >> 5, c8 = (idx & 31) * 8;
        cp_async16(sbB + (uint32_t)(r * LDT + c8) * 2,
                   src + (size_t)(rowoff + r) * 256 + c8, 16);
    }
}

// warp MMA over ks in [ks0, ks1), accumulating into c
__device__ __forceinline__ void mma_krange_f16(uint32_t sb, int m0, int n0,
                                               int ks0, int ks1, float c[4][4])
{
    const int lane = threadIdx.x & 31;
    uint32_t aA = sb + OFF_A + (uint32_t)((m0 + (lane & 15)) * LDT + ((lane >> 4) & 1) * 8) * 2 + ks0 * 32;
    uint32_t aB = sb + OFF_B + (uint32_t)((n0 + (lane & 7)) * LDT + ((lane >> 3) & 1) * 8) * 2 + ks0 * 32;
    for (int ks = ks0; ks < ks1; ++ks) {
        uint32_t fA[4];
        ldsm_x4(aA, fA);
#pragma unroll
        for (int g = 0; g < 4; ++g) {
            uint32_t b[2];
            ldsm_x2(aB + g * 8 * LDT * 2, b);
            mma_f16(c[g], fA, b);
        }
        aA += 32; aB += 32;
    }
}

// ================= GEMM1 (x @ W1) + el1/er1, 4 head-tiles per CTA; fs1 stored fp16 =========
__global__ void __launch_bounds__(512, 2) gemm1_mma_kernel(const float* __restrict__ x,
                                                           const float* __restrict__ al1,
                                                           const float* __restrict__ ar1)
{
    extern __shared__ __align__(16) char dsm[];
    __shared__ float als[256], ars[256];
    __shared__ float elp[2][128], erp[2][128];

    const uint32_t sb = smem_to_u32(dsm);
    const int tid  = threadIdx.x;
    const int lane = tid & 31;
    const int wid  = tid >> 5;
    const int wm = wid >> 1, wn = wid & 1;
    const int m0 = wm * 16, n0 = wn * 32;
    const int row0 = blockIdx.x * 128;

    __half* Aa = reinterpret_cast<__half*>(dsm + OFF_A);

    cp_B_half(g_w1h, 0, sb + OFF_B, tid);
    CP_COMMIT();
    load_A_fp16(x, row0, Aa, tid);
    if (tid < 256) { als[tid] = al1[tid]; ars[tid] = ar1[tid]; }

#pragma unroll 1
    for (int ct = 0; ct < 4; ++ct) {
        const int col0 = ct * 64;
        CP_WAIT(0);
        __syncthreads();

        float c[4][4];
#pragma unroll
        for (int g = 0; g < 4; ++g)
#pragma unroll
            for (int q = 0; q < 4; ++q) c[g][q] = 0.f;
        mma_krange_f16(sb, m0, n0, 0, 16, c);

        __syncthreads();
        if (ct < 3) {
            cp_B_half(g_w1h, col0 + 64, sb + OFF_B, tid);
            CP_COMMIT();
        }

        const int r0 = row0 + m0 + (lane >> 2);
        const int cbl = n0 + 2 * (lane & 3);
        float pel0 = 0.f, per0 = 0.f, pel8 = 0.f, per8 = 0.f;
#pragma unroll
        for (int g = 0; g < 4; ++g) {
            float a0 = als[col0 + cbl + g * 8], a1 = als[col0 + cbl + g * 8 + 1];
            float b0 = ars[col0 + cbl + g * 8], b1 = ars[col0 + cbl + g * 8 + 1];
            pel0 += c[g][0] * a0 + c[g][1] * a1;
            per0 += c[g][0] * b0 + c[g][1] * b1;
            pel8 += c[g][2] * a0 + c[g][3] * a1;
            per8 += c[g][2] * b0 + c[g][3] * b1;
            if (r0 < NN)
                *reinterpret_cast<__half2*>(g_fs1 + (size_t)r0 * 256 + col0 + cbl + g * 8) =
                    __floats2half2_rn(c[g][0], c[g][1]);
            if (r0 + 8 < NN)
                *reinterpret_cast<__half2*>(g_fs1 + (size_t)(r0 + 8) * 256 + col0 + cbl + g * 8) =
                    __floats2half2_rn(c[g][2], c[g][3]);
        }
        pel0 += __shfl_xor_sync(0xffffffffu, pel0, 1); pel0 += __shfl_xor_sync(0xffffffffu, pel0, 2);
        per0 += __shfl_xor_sync(0xffffffffu, per0, 1); per0 += __shfl_xor_sync(0xffffffffu, per0, 2);
        pel8 += __shfl_xor_sync(0xffffffffu, pel8, 1); pel8 += __shfl_xor_sync(0xffffffffu, pel8, 2);
        per8 += __shfl_xor_sync(0xffffffffu, per8, 1); per8 += __shfl_xor_sync(0xffffffffu, per8, 2);
        if ((lane & 3) == 0) {
            int rr = m0 + (lane >> 2);
            elp[wn][rr] = pel0; elp[wn][rr + 8] = pel8;
            erp[wn][rr] = per0; erp[wn][rr + 8] = per8;
        }
        __syncthreads();
        if (tid < 128) {
            int row = row0 + tid;
            if (row < NN) {
                g_el1[row * 4 + ct] = elp[0][tid] + elp[1][tid];
                g_er1[row * 4 + ct] = erp[0][tid] + erp[1][tid];
            }
        }
    }
}

// ================= GEMM2 (h2 @ W2) + el2/er2; 2-stage K-pipelined cp.async ==============
__global__ void __launch_bounds__(512, 2) gemm2_mma_kernel(const float* __restrict__ al2,
                                                           const float* __restrict__ ar2)
{
    extern __shared__ __align__(16) char dsm[];
    __shared__ float als[64], ars[64];
    __shared__ float elp[2][128], erp[2][128];

    const uint32_t sb = smem_to_u32(dsm);
    const int tid  = threadIdx.x;
    const int lane = tid & 31;
    const int wid  = tid >> 5;
    const int wm = wid >> 1, wn = wid & 1;
    const int m0 = wm * 16, n0 = wn * 32;
    const int row0 = blockIdx.x * 128;

    cp_A_half_chunk(g_h2, row0, sb + OFF_A, tid, 0);
    cp_B_half_chunk(g_w2h, 0, sb + OFF_B, tid, 0);
    CP_COMMIT();
    cp_A_half_chunk(g_h2, row0, sb + OFF_A, tid, 1);
    cp_B_half_chunk(g_w2h, 0, sb + OFF_B, tid, 1);
    CP_COMMIT();
    if (tid < 64) {
        als[tid] = (tid < C2) ? al2[tid] : 0.f;
        ars[tid] = (tid < C2) ? ar2[tid] : 0.f;
    }

    float c[4][4];
#pragma unroll
    for (int g = 0; g < 4; ++g)
#pragma unroll
        for (int q = 0; q < 4; ++q) c[g][q] = 0.f;

    CP_WAIT(1);
    __syncthreads();
    mma_krange_f16(sb, m0, n0, 0, 8, c);
    CP_WAIT(0);
    __syncthreads();
    mma_krange_f16(sb, m0, n0, 8, 16, c);

    const int r0 = row0 + m0 + (lane >> 2);
    const int cbl = n0 + 2 * (lane & 3);
    float pel0 = 0.f, per0 = 0.f, pel8 = 0.f, per8 = 0.f;
#pragma unroll
    for (int g = 0; g < 4; ++g) {
        int cc = cbl + g * 8;
        float a0 = als[cc], a1 = als[cc + 1];
        float b0 = ars[cc], b1 = ars[cc + 1];
        pel0 += c[g][0] * a0 + c[g][1] * a1;
        per0 += c[g][0] * b0 + c[g][1] * b1;
        pel8 += c[g][2] * a0 + c[g][3] * a1;
        per8 += c[g][2] * b0 + c[g][3] * b1;
        if (r0 < NN)
            *reinterpret_cast<__half2*>(g_fs2h + (size_t)r0 * 64 + cc) =
                __floats2half2_rn(c[g][0], c[g][1]);
        if (r0 + 8 < NN)
            *reinterpret_cast<__half2*>(g_fs2h + (size_t)(r0 + 8) * 64 + cc) =
                __floats2half2_rn(c[g][2], c[g][3]);
    }
    pel0 += __shfl_xor_sync(0xffffffffu, pel0, 1); pel0 += __shfl_xor_sync(0xffffffffu, pel0, 2);
    per0 += __shfl_xor_sync(0xffffffffu, per0, 1); per0 += __shfl_xor_sync(0xffffffffu, per0, 2);
    pel8 += __shfl_xor_sync(0xffffffffu, pel8, 1); pel8 += __shfl_xor_sync(0xffffffffu, pel8, 2);
    per8 += __shfl_xor_sync(0xffffffffu, per8, 1); per8 += __shfl_xor_sync(0xffffffffu, per8, 2);
    if ((lane & 3) == 0) {
        int rr = m0 + (lane >> 2);
        elp[wn][rr] = pel0; elp[wn][rr + 8] = pel8;
        erp[wn][rr] = per0; erp[wn][rr + 8] = per8;
    }
    __syncthreads();
    if (tid < 128) {
        int row = row0 + tid;
        if (row < NN) {
            g_el2[row] = elp[0][tid] + elp[1][tid];
            g_er2[row] = erp[0][tid] + erp[1][tid];
        }
    }
}

// ---------------- layer-1 aggregation: WARP per node, pipelined, den via warp reduce -----
__global__ void __launch_bounds__(128, 8) agg1_kernel(const int* __restrict__ src,
                                                      const float* __restrict__ b1)
{
    __shared__ __half2 smwh[4][32][4];
    __shared__ int     smsrc[4][32];

    const int w    = threadIdx.x >> 5;
    const int lane = threadIdx.x & 31;
    const int n    = blockIdx.x * 4 + w;
    const int s = g_rowptr[n];
    const int e = g_rowptr[n + 1];
    const float4 er = *reinterpret_cast<const float4*>(g_er1 + n * 4);

    const int h = lane >> 3;
    float2 acc2[4];
#pragma unroll
    for (int q = 0; q < 4; ++q) acc2[q] = make_float2(0.f, 0.f);
    float den = 0.f;

    for (int base = s; base < e; base += 32) {
        int cnt = min(32, e - base);
        // weight phase: pad lanes >= cnt with weight 0, src 0
        float4 wv = make_float4(0.f, 0.f, 0.f, 0.f);
        int sj = 0;
        if (lane < cnt) {
            sj = src[base + lane];
            float4 el = *reinterpret_cast<const float4*>(g_el1 + sj * 4);
            float v;
            v = el.x + er.x; v = v > 0.f ? v : 0.2f * v; wv.x = __expf(v);
            v = el.y + er.y; v = v > 0.f ? v : 0.2f * v; wv.y = __expf(v);
            v = el.z + er.z; v = v > 0.f ? v : 0.2f * v; wv.z = __expf(v);
            v = el.w + er.w; v = v > 0.f ? v : 0.2f * v; wv.w = __expf(v);
        }
        smsrc[w][lane] = sj;
        __half2 wh0 = __float2half2_rn(wv.x);
        __half2 wh1 = __float2half2_rn(wv.y);
        __half2 wh2 = __float2half2_rn(wv.z);
        __half2 wh3 = __float2half2_rn(wv.w);
        uint4 packed;
        packed.x = *reinterpret_cast<uint32_t*>(&wh0);
        packed.y = *reinterpret_cast<uint32_t*>(&wh1);
        packed.z = *reinterpret_cast<uint32_t*>(&wh2);
        packed.w = *reinterpret_cast<uint32_t*>(&wh3);
        *reinterpret_cast<uint4*>(&smwh[w][lane][0]) = packed;
        // chunk denominator: one butterfly reduce instead of per-edge adds
#pragma unroll
        for (int off = 16; off; off >>= 1) {
            wv.x += __shfl_xor_sync(0xffffffffu, wv.x, off);
            wv.y += __shfl_xor_sync(0xffffffffu, wv.y, off);
            wv.z += __shfl_xor_sync(0xffffffffu, wv.z, off);
            wv.w += __shfl_xor_sync(0xffffffffu, wv.w, off);
        }
        den += (h == 0) ? wv.x : (h == 1) ? wv.y : (h == 2) ? wv.z : wv.w;
        __syncwarp();

        const int cnt4 = (cnt + 3) & ~3;
        uint4   fc[4];
        __half2 wc[4];
#pragma unroll
        for (int t = 0; t < 4; ++t) {
            wc[t] = smwh[w][t][h];
            fc[t] = *reinterpret_cast<const uint4*>(
                g_fs1 + (size_t)smsrc[w][t] * 256 + lane * 8);
        }
        int j0 = 0;
#pragma unroll 1
        for (; j0 + 4 < cnt4; j0 += 4) {
            uint4   fn[4];
            __half2 wn[4];
#pragma unroll
            for (int t = 0; t < 4; ++t) {
                wn[t] = smwh[w][j0 + 4 + t][h];
                fn[t] = *reinterpret_cast<const uint4*>(
                    g_fs1 + (size_t)smsrc[w][j0 + 4 + t] * 256 + lane * 8);
            }
            __half2 hacc[4];
            {
                const __half2* hp = reinterpret_cast<const __half2*>(&fc[0]);
#pragma unroll
                for (int q = 0; q < 4; ++q) hacc[q] = __hmul2(wc[0], hp[q]);
            }
#pragma unroll
            for (int t = 1; t < 4; ++t) {
                const __half2* hp = reinterpret_cast<const __half2*>(&fc[t]);
#pragma unroll
                for (int q = 0; q < 4; ++q) hacc[q] = __hfma2(wc[t], hp[q], hacc[q]);
            }
#pragma unroll
            for (int q = 0; q < 4; ++q) {
                float2 fa = __half22float2(hacc[q]);
                acc2[q].x += fa.x; acc2[q].y += fa.y;
            }
#pragma unroll
            for (int t = 0; t < 4; ++t) { fc[t] = fn[t]; wc[t] = wn[t]; }
        }
        {
            __half2 hacc[4];
            {
                const __half2* hp = reinterpret_cast<const __half2*>(&fc[0]);
#pragma unroll
                for (int q = 0; q < 4; ++q) hacc[q] = __hmul2(wc[0], hp[q]);
            }
#pragma unroll
            for (int t = 1; t < 4; ++t) {
                const __half2* hp = reinterpret_cast<const __half2*>(&fc[t]);
#pragma unroll
                for (int q = 0; q < 4; ++q) hacc[q] = __hfma2(wc[t], hp[q], hacc[q]);
            }
#pragma unroll
            for (int q = 0; q < 4; ++q) {
                float2 fa = __half22float2(hacc[q]);
                acc2[q].x += fa.x; acc2[q].y += fa.y;
            }
        }
        __syncwarp();
    }

    float rden = (e > s) ? 1.f / den : 0.f;
    float4 bb0 = *reinterpret_cast<const float4*>(b1 + lane * 8);
    float4 bb1 = *reinterpret_cast<const float4*>(b1 + lane * 8 + 4);
    __half2 o[4];
    o[0] = __floats2half2_rn(fmaxf(acc2[0].x * rden + bb0.x, 0.f), fmaxf(acc2[0].y * rden + bb0.y, 0.f));
    o[1] = __floats2half2_rn(fmaxf(acc2[1].x * rden + bb0.z, 0.f), fmaxf(acc2[1].y * rden + bb0.w, 0.f));
    o[2] = __floats2half2_rn(fmaxf(acc2[2].x * rden + bb1.x, 0.f), fmaxf(acc2[2].y * rden + bb1.y, 0.f));
    o[3] = __floats2half2_rn(fmaxf(acc2[3].x * rden + bb1.z, 0.f), fmaxf(acc2[3].y * rden + bb1.w, 0.f));
    *reinterpret_cast<uint4*>(g_h2 + (size_t)n * 256 + lane * 8) = *reinterpret_cast<uint4*>(o);
}

// ---------------- layer-2 aggregation: WARP per node, pipelined, den via warp reduce -----
__global__ void __launch_bounds__(128, 12) agg2_kernel(const int* __restrict__ src,
                                                       const float* __restrict__ b2,
                                                       float* __restrict__ out)
{
    __shared__ __half2 smwh[4][32];
    __shared__ int     smsrc[4][32];

    const int w    = threadIdx.x >> 5;
    const int lane = threadIdx.x & 31;
    const int n    = blockIdx.x * 4 + w;
    const int s = g_rowptr[n];
    const int e = g_rowptr[n + 1];
    const float ern = g_er2[n];

    float2 acc = make_float2(0.f, 0.f);
    float den = 0.f;
    for (int base = s; base < e; base += 32) {
        int cnt = min(32, e - base);
        float wv = 0.f; int sj = 0;
        if (lane < cnt) {
            sj = src[base + lane];
            float v = g_el2[sj] + ern;
            v = v > 0.f ? v : 0.2f * v;
            wv = __expf(v);
        }
        smsrc[w][lane] = sj;
        smwh[w][lane] = __float2half2_rn(wv);
        // chunk denominator via butterfly reduce
        float ws = wv;
#pragma unroll
        for (int off = 16; off; off >>= 1)
            ws += __shfl_xor_sync(0xffffffffu, ws, off);
        den += ws;
        __syncwarp();

        const int cnt4 = (cnt + 3) & ~3;
        __half2 fc[4], wc[4];
#pragma unroll
        for (int t = 0; t < 4; ++t) {
            wc[t] = smwh[w][t];
            fc[t] = *reinterpret_cast<const __half2*>(
                g_fs2h + (size_t)smsrc[w][t] * 64 + lane * 2);
        }
        int j0 = 0;
#pragma unroll 1
        for (; j0 + 4 < cnt4; j0 += 4) {
            __half2 fn[4], wn[4];
#pragma unroll
            for (int t = 0; t < 4; ++t) {
                wn[t] = smwh[w][j0 + 4 + t];
                fn[t] = *reinterpret_cast<const __half2*>(
                    g_fs2h + (size_t)smsrc[w][j0 + 4 + t] * 64 + lane * 2);
            }
            __half2 hacc = __hmul2(wc[0], fc[0]);
#pragma unroll
            for (int t = 1; t < 4; ++t)
                hacc = __hfma2(wc[t], fc[t], hacc);
            float2 fa = __half22float2(hacc);
            acc.x += fa.x; acc.y += fa.y;
#pragma unroll
            for (int t = 0; t < 4; ++t) { fc[t] = fn[t]; wc[t] = wn[t]; }
        }
        {
            __half2 hacc = __hmul2(wc[0], fc[0]);
#pragma unroll
            for (int t = 1; t < 4; ++t)
                hacc = __hfma2(wc[t], fc[t], hacc);
            float2 fa = __half22float2(hacc);
            acc.x += fa.x; acc.y += fa.y;
        }
        __syncwarp();
    }

    float rden = (e > s) ? 1.f / den : 0.f;
    float* orow = out + (size_t)n * C2;
    int cc = lane * 2;
    if (cc < C2)     orow[cc]     = acc.x * rden + b2[cc];
    if (cc + 1 < C2) orow[cc + 1] = acc.y * rden + b2[cc + 1];
}

// ---------------- launch ----------------
extern "C" void kernel_launch(void* const* d_in, const int* in_sizes, int n_in,
                              void* d_out, int out_size)
{
    const float* x   = (const float*)d_in[0];
    const float* W1  = (const float*)d_in[1];
    const float* al1 = (const float*)d_in[2];
    const float* ar1 = (const float*)d_in[3];
    const float* b1  = (const float*)d_in[4];
    const float* W2  = (const float*)d_in[5];
    const float* al2 = (const float*)d_in[6];
    const float* ar2 = (const float*)d_in[7];
    const float* b2  = (const float*)d_in[8];
    const int*   src = (const int*)d_in[9];
    const int*   dst = (const int*)d_in[10];
    float* out = (float*)d_out;

    (void)in_sizes; (void)n_in; (void)out_size;

    cudaFuncSetAttribute(gemm1_mma_kernel,
                         cudaFuncAttributeMaxDynamicSharedMemorySize, GEMM_SMEM);
    cudaFuncSetAttribute(gemm2_mma_kernel,
                         cudaFuncAttributeMaxDynamicSharedMemorySize, GEMM_SMEM);

    prep_kernel<<<20 + PREP_ROWPTR_BLOCKS, 256>>>(W1, W2, dst);

    // Layer 1
    gemm1_mma_kernel<<<NN_PAD / 128, 512, GEMM_SMEM>>>(x, al1, ar1);
    agg1_kernel<<<NN / 4, 128>>>(src, b1);

    // Layer 2
    gemm2_mma_kernel<<<NN_PAD / 128, 512, GEMM_SMEM>>>(al2, ar2);
    agg2_kernel<<<NN / 4, 128>>>(src, b2, out);
}

// round 16
// speedup vs baseline: 1.0595x; 1.0120x over previous
#include <cuda_runtime.h>
#include <cuda_fp16.h>
#include <cstdint>

#define NN  50000
#define NE  800000
#define NN_PAD 50048              // 391 * 128
#define FIN 256
#define H1  4
#define D1  64
#define C2  47

// ---------------- scratch (device globals; no allocation allowed) ----------------
__device__ __align__(16) __half g_fs1[(size_t)NN * FIN];   // layer-1 features, fp16
__device__ __align__(16) __half g_h2 [(size_t)NN * FIN];   // relu(layer-1 out), fp16
__device__ __align__(16) __half g_fs2h[(size_t)NN * 64];   // layer-2 features, fp16 padded
__device__ __align__(16) float g_el1[NN * H1];
__device__ __align__(16) float g_er1[NN * H1];
__device__ __align__(16) float g_el2[NN];
__device__ __align__(16) float g_er2[NN];
__device__ __align__(16) int   g_rowptr[NN + 1];
// fp16 transposed weights: W1^T [256,256], W2^T padded [64,256]
__device__ __align__(16) __half g_w1h[256 * 256];
__device__ __align__(16) __half g_w2h[64 * 256];

// ================= warp-level MMA helpers (arch-agnostic PTX, sm_80+) =================
__device__ __forceinline__ uint32_t smem_to_u32(const void* p) {
    uint32_t a;
    asm("{ .reg .u64 t; cvta.to.shared.u64 t, %1; cvt.u32.u64 %0, t; }" : "=r"(a) : "l"(p));
    return a;
}
__device__ __forceinline__ void ldsm_x4(uint32_t addr, uint32_t r[4]) {
    asm volatile("ldmatrix.sync.aligned.m8n8.x4.shared.b16 {%0,%1,%2,%3}, [%4];"
                 : "=r"(r[0]), "=r"(r[1]), "=r"(r[2]), "=r"(r[3]) : "r"(addr));
}
__device__ __forceinline__ void ldsm_x2(uint32_t addr, uint32_t r[2]) {
    asm volatile("ldmatrix.sync.aligned.m8n8.x2.shared.b16 {%0,%1}, [%2];"
                 : "=r"(r[0]), "=r"(r[1]) : "r"(addr));
}
__device__ __forceinline__ void mma_f16(float c[4], const uint32_t a[4], const uint32_t b[2]) {
    asm volatile("mma.sync.aligned.m16n8k16.row.col.f32.f16.f16.f32 "
                 "{%0,%1,%2,%3}, {%4,%5,%6,%7}, {%8,%9}, {%0,%1,%2,%3};"
                 : "+f"(c[0]), "+f"(c[1]), "+f"(c[2]), "+f"(c[3])
                 : "r"(a[0]), "r"(a[1]), "r"(a[2]), "r"(a[3]), "r"(b[0]), "r"(b[1]));
}
// ---- cp.async (sm_80+): 16B global->shared, src_bytes<16 zero-fills ----
__device__ __forceinline__ void cp_async16(uint32_t saddr, const void* gaddr, int src_bytes) {
    asm volatile("cp.async.cg.shared.global [%0], [%1], 16, %2;"
                 :: "r"(saddr), "l"(gaddr), "r"(src_bytes) : "memory");
}
#define CP_COMMIT() asm volatile("cp.async.commit_group;" ::: "memory")
#define CP_WAIT(n)  asm volatile("cp.async.wait_group %0;" :: "n"(n) : "memory")

// ================= prep: coalesced W transposes (smem tiles) + CSR rowptr =================
#define PREP_ROWPTR_BLOCKS ((NN + 1 + 255) / 256)
__global__ void prep_kernel(const float* __restrict__ W1, const float* __restrict__ W2,
                            const int* __restrict__ dst)
{
    const int b = blockIdx.x;
    const int tid = threadIdx.x;
    if (b < 20) {
        __shared__ float ts[64][65];
        if (b < 16) {
            const int k0 = (b >> 2) * 64, n0 = (b & 3) * 64;
#pragma unroll
            for (int i = 0; i < 16; ++i) {
                int e = tid + i * 256;
                int r = e >> 6, c = e & 63;
                ts[r][c] = W1[(size_t)(k0 + r) * 256 + n0 + c];
            }
            __syncthreads();
#pragma unroll
            for (int i = 0; i < 16; ++i) {
                int e = tid + i * 256;
                int r2 = e >> 6, c2 = e & 63;
                g_w1h[(size_t)(n0 + r2) * 256 + k0 + c2] = __float2half_rn(ts[c2][r2]);
            }
        } else {
            const int k0 = (b - 16) * 64;
#pragma unroll
            for (int i = 0; i < 16; ++i) {
                int e = tid + i * 256;
                int r = e >> 6, c = e & 63;
                ts[r][c] = (c < C2) ? W2[(size_t)(k0 + r) * C2 + c] : 0.f;
            }
            __syncthreads();
#pragma unroll
            for (int i = 0; i < 16; ++i) {
                int e = tid + i * 256;
                int r2 = e >> 6, c2 = e & 63;
                g_w2h[(size_t)r2 * 256 + k0 + c2] = __float2half_rn(ts[c2][r2]);
            }
        }
    } else {
        int n = (b - 20) * 256 + tid;
        if (n > NN) return;
        int lo = 0, hi = NE;
        while (lo < hi) {
            int mid = (lo + hi) >> 1;
            if (dst[mid] < n) lo = mid + 1; else hi = mid;
        }
        g_rowptr[n] = lo;
    }
}

// ================= fused GEMM + attention-logit kernels (single fp16 term) =============
#define LDT 264                       // padded row stride in 16-bit elems (528 B)
#define OFF_A 0
#define OFF_B (128 * LDT * 2)         // 67584
#define GEMM_SMEM (OFF_B + 64 * LDT * 2)   // 101376 B dynamic -> 2 CTAs/SM

__device__ __forceinline__ void load_A_fp16(const float* __restrict__ src, int row0,
                                            __half* Aa, int tid)
{
#pragma unroll
    for (int i = 0; i < 16; ++i) {
        int idx = tid + i * 512;
        int r = idx >> 6, q = (idx & 63) * 4;
        int gr = row0 + r;
        float4 v = make_float4(0.f, 0.f, 0.f, 0.f);
        if (gr < NN) v = *reinterpret_cast<const float4*>(src + (size_t)gr * 256 + q);
        __half2 p0 = __floats2half2_rn(v.x, v.y);
        __half2 p1 = __floats2half2_rn(v.z, v.w);
        *reinterpret_cast<uint2*>(Aa + r * LDT + q) =
            make_uint2(*reinterpret_cast<uint32_t*>(&p0), *reinterpret_cast<uint32_t*>(&p1));
    }
}
__device__ __forceinline__ void cp_A_half_chunk(const __half* __restrict__ src, int row0,
                                                uint32_t sbA, int tid, int chunk)
{
#pragma unroll
    for (int i = 0; i < 4; ++i) {
        int idx = tid + i * 512;
        int r = idx >> 4, c8 = (idx & 15) * 8 + chunk * 128;
        int gr = row0 + r;
        cp_async16(sbA + (uint32_t)(r * LDT + c8) * 2,
                   src + (size_t)gr * 256 + c8, (gr < NN) ? 16 : 0);
    }
}
__device__ __forceinline__ void cp_B_half_chunk(const __half* __restrict__ src, int rowoff,
                                                uint32_t sbB, int tid, int chunk)
{
#pragma unroll
    for (int i = 0; i < 2; ++i) {
        int idx = tid + i * 512;
        int r = idx >> 4, c8 = (idx & 15) * 8 + chunk * 128;
        cp_async16(sbB + (uint32_t)(r * LDT + c8) * 2,
                   src + (size_t)(rowoff + r) * 256 + c8, 16);
    }
}
__device__ __forceinline__ void cp_B_half(const __half* __restrict__ src, int rowoff,
                                          uint32_t sbB, int tid)
{
#pragma unroll
    for (int i = 0; i < 4; ++i) {
        int idx = tid + i * 512;
        int r = idx >> 5, c8 = (idx & 31) * 8;
        cp_async16(sbB + (uint32_t)(r * LDT + c8) * 2,
                   src + (size_t)(rowoff + r) * 256 + c8, 16);
    }
}

// warp MMA over ks in [ks0, ks1), accumulating into c
__device__ __forceinline__ void mma_krange_f16(uint32_t sb, int m0, int n0,
                                               int ks0, int ks1, float c[4][4])
{
    const int lane = threadIdx.x & 31;
    uint32_t aA = sb + OFF_A + (uint32_t)((m0 + (lane & 15)) * LDT + ((lane >> 4) & 1) * 8) * 2 + ks0 * 32;
    uint32_t aB = sb + OFF_B + (uint32_t)((n0 + (lane & 7)) * LDT + ((lane >> 3) & 1) * 8) * 2 + ks0 * 32;
    for (int ks = ks0; ks < ks1; ++ks) {
        uint32_t fA[4];
        ldsm_x4(aA, fA);
#pragma unroll
        for (int g = 0; g < 4; ++g) {
            uint32_t b[2];
            ldsm_x2(aB + g * 8 * LDT * 2, b);
            mma_f16(c[g], fA, b);
        }
        aA += 32; aB += 32;
    }
}

// ================= GEMM1 (x @ W1) + el1/er1, 4 head-tiles per CTA; fs1 stored fp16 =========
__global__ void __launch_bounds__(512, 2) gemm1_mma_kernel(const float* __restrict__ x,
                                                           const float* __restrict__ al1,
                                                           const float* __restrict__ ar1)
{
    extern __shared__ __align__(16) char dsm[];
    __shared__ float als[256], ars[256];
    __shared__ float elp[2][128], erp[2][128];

    const uint32_t sb = smem_to_u32(dsm);
    const int tid  = threadIdx.x;
    const int lane = tid & 31;
    const int wid  = tid >> 5;
    const int wm = wid >> 1, wn = wid & 1;
    const int m0 = wm * 16, n0 = wn * 32;
    const int row0 = blockIdx.x * 128;

    __half* Aa = reinterpret_cast<__half*>(dsm + OFF_A);

    cp_B_half(g_w1h, 0, sb + OFF_B, tid);
    CP_COMMIT();
    load_A_fp16(x, row0, Aa, tid);
    if (tid < 256) { als[tid] = al1[tid]; ars[tid] = ar1[tid]; }

#pragma unroll 1
    for (int ct = 0; ct < 4; ++ct) {
        const int col0 = ct * 64;
        CP_WAIT(0);
        __syncthreads();

        float c[4][4];
#pragma unroll
        for (int g = 0; g < 4; ++g)
#pragma unroll
            for (int q = 0; q < 4; ++q) c[g][q] = 0.f;
        mma_krange_f16(sb, m0, n0, 0, 16, c);

        __syncthreads();
        if (ct < 3) {
            cp_B_half(g_w1h, col0 + 64, sb + OFF_B, tid);
            CP_COMMIT();
        }

        const int r0 = row0 + m0 + (lane >> 2);
        const int cbl = n0 + 2 * (lane & 3);
        float pel0 = 0.f, per0 = 0.f, pel8 = 0.f, per8 = 0.f;
#pragma unroll
        for (int g = 0; g < 4; ++g) {
            float a0 = als[col0 + cbl + g * 8], a1 = als[col0 + cbl + g * 8 + 1];
            float b0 = ars[col0 + cbl + g * 8], b1 = ars[col0 + cbl + g * 8 + 1];
            pel0 += c[g][0] * a0 + c[g][1] * a1;
            per0 += c[g][0] * b0 + c[g][1] * b1;
            pel8 += c[g][2] * a0 + c[g][3] * a1;
            per8 += c[g][2] * b0 + c[g][3] * b1;
            if (r0 < NN)
                *reinterpret_cast<__half2*>(g_fs1 + (size_t)r0 * 256 + col0 + cbl + g * 8) =
                    __floats2half2_rn(c[g][0], c[g][1]);
            if (r0 + 8 < NN)
                *reinterpret_cast<__half2*>(g_fs1 + (size_t)(r0 + 8) * 256 + col0 + cbl + g * 8) =
                    __floats2half2_rn(c[g][2], c[g][3]);
        }
        pel0 += __shfl_xor_sync(0xffffffffu, pel0, 1); pel0 += __shfl_xor_sync(0xffffffffu, pel0, 2);
        per0 += __shfl_xor_sync(0xffffffffu, per0, 1); per0 += __shfl_xor_sync(0xffffffffu, per0, 2);
        pel8 += __shfl_xor_sync(0xffffffffu, pel8, 1); pel8 += __shfl_xor_sync(0xffffffffu, pel8, 2);
        per8 += __shfl_xor_sync(0xffffffffu, per8, 1); per8 += __shfl_xor_sync(0xffffffffu, per8, 2);
        if ((lane & 3) == 0) {
            int rr = m0 + (lane >> 2);
            elp[wn][rr] = pel0; elp[wn][rr + 8] = pel8;
            erp[wn][rr] = per0; erp[wn][rr + 8] = per8;
        }
        __syncthreads();
        if (tid < 128) {
            int row = row0 + tid;
            if (row < NN) {
                g_el1[row * 4 + ct] = elp[0][tid] + elp[1][tid];
                g_er1[row * 4 + ct] = erp[0][tid] + erp[1][tid];
            }
        }
    }
}

// ================= GEMM2 (h2 @ W2) + el2/er2; 2-stage K-pipelined cp.async ==============
__global__ void __launch_bounds__(512, 2) gemm2_mma_kernel(const float* __restrict__ al2,
                                                           const float* __restrict__ ar2)
{
    extern __shared__ __align__(16) char dsm[];
    __shared__ float als[64], ars[64];
    __shared__ float elp[2][128], erp[2][128];

    const uint32_t sb = smem_to_u32(dsm);
    const int tid  = threadIdx.x;
    const int lane = tid & 31;
    const int wid  = tid >> 5;
    const int wm = wid >> 1, wn = wid & 1;
    const int m0 = wm * 16, n0 = wn * 32;
    const int row0 = blockIdx.x * 128;

    cp_A_half_chunk(g_h2, row0, sb + OFF_A, tid, 0);
    cp_B_half_chunk(g_w2h, 0, sb + OFF_B, tid, 0);
    CP_COMMIT();
    cp_A_half_chunk(g_h2, row0, sb + OFF_A, tid, 1);
    cp_B_half_chunk(g_w2h, 0, sb + OFF_B, tid, 1);
    CP_COMMIT();
    if (tid < 64) {
        als[tid] = (tid < C2) ? al2[tid] : 0.f;
        ars[tid] = (tid < C2) ? ar2[tid] : 0.f;
    }

    float c[4][4];
#pragma unroll
    for (int g = 0; g < 4; ++g)
#pragma unroll
        for (int q = 0; q < 4; ++q) c[g][q] = 0.f;

    CP_WAIT(1);
    __syncthreads();
    mma_krange_f16(sb, m0, n0, 0, 8, c);
    CP_WAIT(0);
    __syncthreads();
    mma_krange_f16(sb, m0, n0, 8, 16, c);

    const int r0 = row0 + m0 + (lane >> 2);
    const int cbl = n0 + 2 * (lane & 3);
    float pel0 = 0.f, per0 = 0.f, pel8 = 0.f, per8 = 0.f;
#pragma unroll
    for (int g = 0; g < 4; ++g) {
        int cc = cbl + g * 8;
        float a0 = als[cc], a1 = als[cc + 1];
        float b0 = ars[cc], b1 = ars[cc + 1];
        pel0 += c[g][0] * a0 + c[g][1] * a1;
        per0 += c[g][0] * b0 + c[g][1] * b1;
        pel8 += c[g][2] * a0 + c[g][3] * a1;
        per8 += c[g][2] * b0 + c[g][3] * b1;
        if (r0 < NN)
            *reinterpret_cast<__half2*>(g_fs2h + (size_t)r0 * 64 + cc) =
                __floats2half2_rn(c[g][0], c[g][1]);
        if (r0 + 8 < NN)
            *reinterpret_cast<__half2*>(g_fs2h + (size_t)(r0 + 8) * 64 + cc) =
                __floats2half2_rn(c[g][2], c[g][3]);
    }
    pel0 += __shfl_xor_sync(0xffffffffu, pel0, 1); pel0 += __shfl_xor_sync(0xffffffffu, pel0, 2);
    per0 += __shfl_xor_sync(0xffffffffu, per0, 1); per0 += __shfl_xor_sync(0xffffffffu, per0, 2);
    pel8 += __shfl_xor_sync(0xffffffffu, pel8, 1); pel8 += __shfl_xor_sync(0xffffffffu, pel8, 2);
    per8 += __shfl_xor_sync(0xffffffffu, per8, 1); per8 += __shfl_xor_sync(0xffffffffu, per8, 2);
    if ((lane & 3) == 0) {
        int rr = m0 + (lane >> 2);
        elp[wn][rr] = pel0; elp[wn][rr + 8] = pel8;
        erp[wn][rr] = per0; erp[wn][rr + 8] = per8;
    }
    __syncthreads();
    if (tid < 128) {
        int row = row0 + tid;
        if (row < NN) {
            g_el2[row] = elp[0][tid] + elp[1][tid];
            g_er2[row] = erp[0][tid] + erp[1][tid];
        }
    }
}

// ---------------- layer-1 aggregation: WARP per node, software-pipelined gather (R13) ----
__global__ void __launch_bounds__(128, 8) agg1_kernel(const int* __restrict__ src,
                                                      const float* __restrict__ b1)
{
    __shared__ __half2 smwh[4][32][4];
    __shared__ int     smsrc[4][32];

    const int w    = threadIdx.x >> 5;
    const int lane = threadIdx.x & 31;
    const int n    = blockIdx.x * 4 + w;
    const int s = g_rowptr[n];
    const int e = g_rowptr[n + 1];
    const float4 er = *reinterpret_cast<const float4*>(g_er1 + n * 4);

    const int h = lane >> 3;
    float2 acc2[4];
#pragma unroll
    for (int q = 0; q < 4; ++q) acc2[q] = make_float2(0.f, 0.f);
    float den = 0.f;

    for (int base = s; base < e; base += 32) {
        int cnt = min(32, e - base);
        float4 wv = make_float4(0.f, 0.f, 0.f, 0.f);
        int sj = 0;
        if (lane < cnt) {
            sj = src[base + lane];
            float4 el = *reinterpret_cast<const float4*>(g_el1 + sj * 4);
            float v;
            v = el.x + er.x; v = v > 0.f ? v : 0.2f * v; wv.x = __expf(v);
            v = el.y + er.y; v = v > 0.f ? v : 0.2f * v; wv.y = __expf(v);
            v = el.z + er.z; v = v > 0.f ? v : 0.2f * v; wv.z = __expf(v);
            v = el.w + er.w; v = v > 0.f ? v : 0.2f * v; wv.w = __expf(v);
        }
        smsrc[w][lane] = sj;
        __half2 wh0 = __float2half2_rn(wv.x);
        __half2 wh1 = __float2half2_rn(wv.y);
        __half2 wh2 = __float2half2_rn(wv.z);
        __half2 wh3 = __float2half2_rn(wv.w);
        uint4 packed;
        packed.x = *reinterpret_cast<uint32_t*>(&wh0);
        packed.y = *reinterpret_cast<uint32_t*>(&wh1);
        packed.z = *reinterpret_cast<uint32_t*>(&wh2);
        packed.w = *reinterpret_cast<uint32_t*>(&wh3);
        *reinterpret_cast<uint4*>(&smwh[w][lane][0]) = packed;
        __syncwarp();

        const int cnt4 = (cnt + 3) & ~3;
        uint4   fc[4];
        __half2 wc[4];
#pragma unroll
        for (int t = 0; t < 4; ++t) {
            wc[t] = smwh[w][t][h];
            fc[t] = *reinterpret_cast<const uint4*>(
                g_fs1 + (size_t)smsrc[w][t] * 256 + lane * 8);
        }
        int j0 = 0;
#pragma unroll 1
        for (; j0 + 4 < cnt4; j0 += 4) {
            uint4   fn[4];
            __half2 wn[4];
#pragma unroll
            for (int t = 0; t < 4; ++t) {
                wn[t] = smwh[w][j0 + 4 + t][h];
                fn[t] = *reinterpret_cast<const uint4*>(
                    g_fs1 + (size_t)smsrc[w][j0 + 4 + t] * 256 + lane * 8);
            }
            __half2 hacc[4];
            {
                const __half2* hp = reinterpret_cast<const __half2*>(&fc[0]);
                den += __low2float(wc[0]);
#pragma unroll
                for (int q = 0; q < 4; ++q) hacc[q] = __hmul2(wc[0], hp[q]);
            }
#pragma unroll
            for (int t = 1; t < 4; ++t) {
                const __half2* hp = reinterpret_cast<const __half2*>(&fc[t]);
                den += __low2float(wc[t]);
#pragma unroll
                for (int q = 0; q < 4; ++q) hacc[q] = __hfma2(wc[t], hp[q], hacc[q]);
            }
#pragma unroll
            for (int q = 0; q < 4; ++q) {
                float2 fa = __half22float2(hacc[q]);
                acc2[q].x += fa.x; acc2[q].y += fa.y;
            }
#pragma unroll
            for (int t = 0; t < 4; ++t) { fc[t] = fn[t]; wc[t] = wn[t]; }
        }
        {
            __half2 hacc[4];
            {
                const __half2* hp = reinterpret_cast<const __half2*>(&fc[0]);
                den += __low2float(wc[0]);
#pragma unroll
                for (int q = 0; q < 4; ++q) hacc[q] = __hmul2(wc[0], hp[q]);
            }
#pragma unroll
            for (int t = 1; t < 4; ++t) {
                const __half2* hp = reinterpret_cast<const __half2*>(&fc[t]);
                den += __low2float(wc[t]);
#pragma unroll
                for (int q = 0; q < 4; ++q) hacc[q] = __hfma2(wc[t], hp[q], hacc[q]);
            }
#pragma unroll
            for (int q = 0; q < 4; ++q) {
                float2 fa = __half22float2(hacc[q]);
                acc2[q].x += fa.x; acc2[q].y += fa.y;
            }
        }
        __syncwarp();
    }

    float rden = (e > s) ? 1.f / den : 0.f;
    float4 bb0 = *reinterpret_cast<const float4*>(b1 + lane * 8);
    float4 bb1 = *reinterpret_cast<const float4*>(b1 + lane * 8 + 4);
    __half2 o[4];
    o[0] = __floats2half2_rn(fmaxf(acc2[0].x * rden + bb0.x, 0.f), fmaxf(acc2[0].y * rden + bb0.y, 0.f));
    o[1] = __floats2half2_rn(fmaxf(acc2[1].x * rden + bb0.z, 0.f), fmaxf(acc2[1].y * rden + bb0.w, 0.f));
    o[2] = __floats2half2_rn(fmaxf(acc2[2].x * rden + bb1.x, 0.f), fmaxf(acc2[2].y * rden + bb1.y, 0.f));
    o[3] = __floats2half2_rn(fmaxf(acc2[3].x * rden + bb1.z, 0.f), fmaxf(acc2[3].y * rden + bb1.w, 0.f));
    *reinterpret_cast<uint4*>(g_h2 + (size_t)n * 256 + lane * 8) = *reinterpret_cast<uint4*>(o);
}

// ---------------- layer-2 aggregation: WARP per node, HALF-WARP edge parallel ----------
// Half-warp g owns edges with parity g; lane covers cols [l16*4, l16*4+4) via uint2 load.
__global__ void __launch_bounds__(128, 12) agg2_kernel(const int* __restrict__ src,
                                                       const float* __restrict__ b2,
                                                       float* __restrict__ out)
{
    __shared__ __half2 smwh[4][32];
    __shared__ int     smsrc[4][32];

    const int w    = threadIdx.x >> 5;
    const int lane = threadIdx.x & 31;
    const int g    = lane >> 4;           // half-warp id
    const int l16  = lane & 15;
    const int n    = blockIdx.x * 4 + w;
    const int s = g_rowptr[n];
    const int e = g_rowptr[n + 1];
    const float ern = g_er2[n];

    float2 accA = make_float2(0.f, 0.f);  // cols l16*4, l16*4+1
    float2 accB = make_float2(0.f, 0.f);  // cols l16*4+2, l16*4+3
    float den = 0.f;

    for (int base = s; base < e; base += 32) {
        int cnt = min(32, e - base);
        float wv = 0.f; int sj = 0;
        if (lane < cnt) {
            sj = src[base + lane];
            float v = g_el2[sj] + ern;
            v = v > 0.f ? v : 0.2f * v;
            wv = __expf(v);
        }
        smsrc[w][lane] = sj;
        smwh[w][lane] = __float2half2_rn(wv);
        // chunk denominator via fp32 butterfly (zero-padded lanes contribute 0)
        float ws = wv;
#pragma unroll
        for (int off = 16; off; off >>= 1)
            ws += __shfl_xor_sync(0xffffffffu, ws, off);
        den += ws;
        __syncwarp();

        // per-half-warp edge count, multiple of 4 (slots are zero-padded to 32)
        const int m = ((cnt + 7) & ~7) >> 1;
        uint2   fc[4];
        __half2 wc[4];
#pragma unroll
        for (int t = 0; t < 4; ++t) {
            int j = 2 * t + g;
            wc[t] = smwh[w][j];
            fc[t] = *reinterpret_cast<const uint2*>(
                g_fs2h + (size_t)smsrc[w][j] * 64 + l16 * 4);
        }
        int i0 = 0;
#pragma unroll 1
        for (; i0 + 4 < m; i0 += 4) {
            uint2   fn[4];
            __half2 wn[4];
#pragma unroll
            for (int t = 0; t < 4; ++t) {
                int j = 2 * (i0 + 4 + t) + g;
                wn[t] = smwh[w][j];
                fn[t] = *reinterpret_cast<const uint2*>(
                    g_fs2h + (size_t)smsrc[w][j] * 64 + l16 * 4);
            }
            __half2 h0 = __hmul2(wc[0], *reinterpret_cast<const __half2*>(&fc[0].x));
            __half2 h1 = __hmul2(wc[0], *reinterpret_cast<const __half2*>(&fc[0].y));
#pragma unroll
            for (int t = 1; t < 4; ++t) {
                h0 = __hfma2(wc[t], *reinterpret_cast<const __half2*>(&fc[t].x), h0);
                h1 = __hfma2(wc[t], *reinterpret_cast<const __half2*>(&fc[t].y), h1);
            }
            float2 fa = __half22float2(h0);
            float2 fb = __half22float2(h1);
            accA.x += fa.x; accA.y += fa.y;
            accB.x += fb.x; accB.y += fb.y;
#pragma unroll
            for (int t = 0; t < 4; ++t) { fc[t] = fn[t]; wc[t] = wn[t]; }
        }
        {
            __half2 h0 = __hmul2(wc[0], *reinterpret_cast<const __half2*>(&fc[0].x));
            __half2 h1 = __hmul2(wc[0], *reinterpret_cast<const __half2*>(&fc[0].y));
#pragma unroll
            for (int t = 1; t < 4; ++t) {
                h0 = __hfma2(wc[t], *reinterpret_cast<const __half2*>(&fc[t].x), h0);
                h1 = __hfma2(wc[t], *reinterpret_cast<const __half2*>(&fc[t].y), h1);
            }
            float2 fa = __half22float2(h0);
            float2 fb = __half22float2(h1);
            accA.x += fa.x; accA.y += fa.y;
            accB.x += fb.x; accB.y += fb.y;
        }
        __syncwarp();
    }

    // merge the two half-warps (lanes l and l+16 hold the same columns)
    accA.x += __shfl_xor_sync(0xffffffffu, accA.x, 16);
    accA.y += __shfl_xor_sync(0xffffffffu, accA.y, 16);
    accB.x += __shfl_xor_sync(0xffffffffu, accB.x, 16);
    accB.y += __shfl_xor_sync(0xffffffffu, accB.y, 16);

    if (g == 0) {
        float rden = (e > s) ? 1.f / den : 0.f;
        float* orow = out + (size_t)n * C2;
        int cc = l16 * 4;
        if (cc     < C2) orow[cc]     = accA.x * rden + b2[cc];
        if (cc + 1 < C2) orow[cc + 1] = accA.y * rden + b2[cc + 1];
        if (cc + 2 < C2) orow[cc + 2] = accB.x * rden + b2[cc + 2];
        if (cc + 3 < C2) orow[cc + 3] = accB.y * rden + b2[cc + 3];
    }
}

// ---------------- launch ----------------
extern "C" void kernel_launch(void* const* d_in, const int* in_sizes, int n_in,
                              void* d_out, int out_size)
{
    const float* x   = (const float*)d_in[0];
    const float* W1  = (const float*)d_in[1];
    const float* al1 = (const float*)d_in[2];
    const float* ar1 = (const float*)d_in[3];
    const float* b1  = (const float*)d_in[4];
    const float* W2  = (const float*)d_in[5];
    const float* al2 = (const float*)d_in[6];
    const float* ar2 = (const float*)d_in[7];
    const float* b2  = (const float*)d_in[8];
    const int*   src = (const int*)d_in[9];
    const int*   dst = (const int*)d_in[10];
    float* out = (float*)d_out;

    (void)in_sizes; (void)n_in; (void)out_size;

    cudaFuncSetAttribute(gemm1_mma_kernel,
                         cudaFuncAttributeMaxDynamicSharedMemorySize, GEMM_SMEM);
    cudaFuncSetAttribute(gemm2_mma_kernel,
                         cudaFuncAttributeMaxDynamicSharedMemorySize, GEMM_SMEM);

    prep_kernel<<<20 + PREP_ROWPTR_BLOCKS, 256>>>(W1, W2, dst);

    // Layer 1
    gemm1_mma_kernel<<<NN_PAD / 128, 512, GEMM_SMEM>>>(x, al1, ar1);
    agg1_kernel<<<NN / 4, 128>>>(src, b1);

    // Layer 2
    gemm2_mma_kernel<<<NN_PAD / 128, 512, GEMM_SMEM>>>(al2, ar2);
    agg2_kernel<<<NN / 4, 128>>>(src, b2, out);
}

// round 17
// speedup vs baseline: 1.1172x; 1.0544x over previous
#include <cuda_runtime.h>
#include <cuda_fp16.h>
#include <cstdint>

#define NN  50000
#define NE  800000
#define NN_PAD 50048              // 391 * 128
#define FIN 256
#define H1  4
#define D1  64
#define C2  47

// ---------------- scratch (device globals; no allocation allowed) ----------------
__device__ __align__(16) __half g_fs1[(size_t)NN * FIN];   // layer-1 features, fp16
__device__ __align__(16) __half g_h2 [(size_t)NN * FIN];   // relu(layer-1 out), fp16
__device__ __align__(16) __half g_fs2h[(size_t)NN * 64];   // layer-2 features, fp16 padded (cols 48..63 stay 0)
__device__ __align__(16) float g_el1[NN * H1];
__device__ __align__(16) float g_er1[NN * H1];
__device__ __align__(16) float g_el2[NN];
__device__ __align__(16) float g_er2[NN];
__device__ __align__(16) int   g_rowptr[NN + 1];
// fp16 transposed weights: W1^T [256,256], W2^T padded [64,256]
__device__ __align__(16) __half g_w1h[256 * 256];
__device__ __align__(16) __half g_w2h[64 * 256];

// ================= warp-level MMA helpers (arch-agnostic PTX, sm_80+) =================
__device__ __forceinline__ uint32_t smem_to_u32(const void* p) {
    uint32_t a;
    asm("{ .reg .u64 t; cvta.to.shared.u64 t, %1; cvt.u32.u64 %0, t; }" : "=r"(a) : "l"(p));
    return a;
}
__device__ __forceinline__ void ldsm_x4(uint32_t addr, uint32_t r[4]) {
    asm volatile("ldmatrix.sync.aligned.m8n8.x4.shared.b16 {%0,%1,%2,%3}, [%4];"
                 : "=r"(r[0]), "=r"(r[1]), "=r"(r[2]), "=r"(r[3]) : "r"(addr));
}
__device__ __forceinline__ void ldsm_x2(uint32_t addr, uint32_t r[2]) {
    asm volatile("ldmatrix.sync.aligned.m8n8.x2.shared.b16 {%0,%1}, [%2];"
                 : "=r"(r[0]), "=r"(r[1]) : "r"(addr));
}
__device__ __forceinline__ void mma_f16(float c[4], const uint32_t a[4], const uint32_t b[2]) {
    asm volatile("mma.sync.aligned.m16n8k16.row.col.f32.f16.f16.f32 "
                 "{%0,%1,%2,%3}, {%4,%5,%6,%7}, {%8,%9}, {%0,%1,%2,%3};"
                 : "+f"(c[0]), "+f"(c[1]), "+f"(c[2]), "+f"(c[3])
                 : "r"(a[0]), "r"(a[1]), "r"(a[2]), "r"(a[3]), "r"(b[0]), "r"(b[1]));
}
// ---- cp.async (sm_80+): 16B global->shared, src_bytes<16 zero-fills ----
__device__ __forceinline__ void cp_async16(uint32_t saddr, const void* gaddr, int src_bytes) {
    asm volatile("cp.async.cg.shared.global [%0], [%1], 16, %2;"
                 :: "r"(saddr), "l"(gaddr), "r"(src_bytes) : "memory");
}
#define CP_COMMIT() asm volatile("cp.async.commit_group;" ::: "memory")
#define CP_WAIT(n)  asm volatile("cp.async.wait_group %0;" :: "n"(n) : "memory")

// ================= prep: coalesced W transposes + rowptr by scatter (sorted dst) ==========
#define PREP_EDGE_BLOCKS ((NE + 255) / 256)
__global__ void prep_kernel(const float* __restrict__ W1, const float* __restrict__ W2,
                            const int* __restrict__ dst)
{
    const int b = blockIdx.x;
    const int tid = threadIdx.x;
    if (b < 20) {
        __shared__ float ts[64][65];
        if (b < 16) {
            const int k0 = (b >> 2) * 64, n0 = (b & 3) * 64;
#pragma unroll
            for (int i = 0; i < 16; ++i) {
                int e = tid + i * 256;
                int r = e >> 6, c = e & 63;
                ts[r][c] = W1[(size_t)(k0 + r) * 256 + n0 + c];
            }
            __syncthreads();
#pragma unroll
            for (int i = 0; i < 16; ++i) {
                int e = tid + i * 256;
                int r2 = e >> 6, c2 = e & 63;
                g_w1h[(size_t)(n0 + r2) * 256 + k0 + c2] = __float2half_rn(ts[c2][r2]);
            }
        } else {
            const int k0 = (b - 16) * 64;
#pragma unroll
            for (int i = 0; i < 16; ++i) {
                int e = tid + i * 256;
                int r = e >> 6, c = e & 63;
                ts[r][c] = (c < C2) ? W2[(size_t)(k0 + r) * C2 + c] : 0.f;
            }
            __syncthreads();
#pragma unroll
            for (int i = 0; i < 16; ++i) {
                int e = tid + i * 256;
                int r2 = e >> 6, c2 = e & 63;
                g_w2h[(size_t)r2 * 256 + k0 + c2] = __float2half_rn(ts[c2][r2]);
            }
        }
    } else {
        // rowptr scatter: rowptr[n] = first edge index with dst >= n
        int j = (b - 20) * 256 + tid;
        if (j >= NE) return;
        int d = dst[j];
        int dnext = (j + 1 < NE) ? dst[j + 1] : NN;
        if (j == 0)
            for (int n = 0; n <= d; ++n) g_rowptr[n] = 0;
        for (int n = d + 1; n <= dnext; ++n) g_rowptr[n] = j + 1;
    }
}

// ================= shared tiling constants =================
#define LDT 264                       // padded row stride in 16-bit elems (528 B)
#define OFF_A 0
#define OFF_B (128 * LDT * 2)         // 67584
#define GEMM_SMEM  (OFF_B + 64 * LDT * 2)   // gemm1: 101376 B
#define GEMM2_SMEM (OFF_B + 48 * LDT * 2)   // gemm2: 92928 B (48-row B tile)

__device__ __forceinline__ void load_A_fp16(const float* __restrict__ src, int row0,
                                            __half* Aa, int tid)
{
#pragma unroll
    for (int i = 0; i < 16; ++i) {
        int idx = tid + i * 512;
        int r = idx >> 6, q = (idx & 63) * 4;
        int gr = row0 + r;
        float4 v = make_float4(0.f, 0.f, 0.f, 0.f);
        if (gr < NN) v = *reinterpret_cast<const float4*>(src + (size_t)gr * 256 + q);
        __half2 p0 = __floats2half2_rn(v.x, v.y);
        __half2 p1 = __floats2half2_rn(v.z, v.w);
        *reinterpret_cast<uint2*>(Aa + r * LDT + q) =
            make_uint2(*reinterpret_cast<uint32_t*>(&p0), *reinterpret_cast<uint32_t*>(&p1));
    }
}
__device__ __forceinline__ void cp_A_half_chunk(const __half* __restrict__ src, int row0,
                                                uint32_t sbA, int tid, int chunk)
{
#pragma unroll
    for (int i = 0; i < 4; ++i) {
        int idx = tid + i * 512;
        int r = idx >> 4, c8 = (idx & 15) * 8 + chunk * 128;
        int gr = row0 + r;
        cp_async16(sbA + (uint32_t)(r * LDT + c8) * 2,
                   src + (size_t)gr * 256 + c8, (gr < NN) ? 16 : 0);
    }
}
// 48-row B tile, K-chunked (768 16B-groups per chunk)
__device__ __forceinline__ void cp_B48_chunk(const __half* __restrict__ src,
                                             uint32_t sbB, int tid, int chunk)
{
#pragma unroll
    for (int i = 0; i < 2; ++i) {
        int idx = tid + i * 512;
        if (idx < 768) {
            int r = idx >> 4, c8 = (idx & 15) * 8 + chunk * 128;
            cp_async16(sbB + (uint32_t)(r * LDT + c8) * 2,
                       src + (size_t)r * 256 + c8, 16);
        }
    }
}
__device__ __forceinline__ void cp_B_half(const __half* __restrict__ src, int rowoff,
                                          uint32_t sbB, int tid)
{
#pragma unroll
    for (int i = 0; i < 4; ++i) {
        int idx = tid + i * 512;
        int r = idx >> 5, c8 = (idx & 31) * 8;
        cp_async16(sbB + (uint32_t)(r * LDT + c8) * 2,
                   src + (size_t)(rowoff + r) * 256 + c8, 16);
    }
}

// warp MMA over ks in [ks0, ks1), NG n-groups of 8, accumulating into c[NG][4]
template <int NG>
__device__ __forceinline__ void mma_krange(uint32_t sb, int m0, int n0,
                                           int ks0, int ks1, float c[][4])
{
    const int lane = threadIdx.x & 31;
    uint32_t aA = sb + OFF_A + (uint32_t)((m0 + (lane & 15)) * LDT + ((lane >> 4) & 1) * 8) * 2 + ks0 * 32;
    uint32_t aB = sb + OFF_B + (uint32_t)((n0 + (lane & 7)) * LDT + ((lane >> 3) & 1) * 8) * 2 + ks0 * 32;
    for (int ks = ks0; ks < ks1; ++ks) {
        uint32_t fA[4];
        ldsm_x4(aA, fA);
#pragma unroll
        for (int g = 0; g < NG; ++g) {
            uint32_t b[2];
            ldsm_x2(aB + g * 8 * LDT * 2, b);
            mma_f16(c[g], fA, b);
        }
        aA += 32; aB += 32;
    }
}

// ================= GEMM1 (x @ W1) + el1/er1, 4 head-tiles per CTA; fs1 stored fp16 =========
__global__ void __launch_bounds__(512, 2) gemm1_mma_kernel(const float* __restrict__ x,
                                                           const float* __restrict__ al1,
                                                           const float* __restrict__ ar1)
{
    extern __shared__ __align__(16) char dsm[];
    __shared__ float als[256], ars[256];
    __shared__ float elp[2][128], erp[2][128];

    const uint32_t sb = smem_to_u32(dsm);
    const int tid  = threadIdx.x;
    const int lane = tid & 31;
    const int wid  = tid >> 5;
    const int wm = wid >> 1, wn = wid & 1;
    const int m0 = wm * 16, n0 = wn * 32;
    const int row0 = blockIdx.x * 128;

    __half* Aa = reinterpret_cast<__half*>(dsm + OFF_A);

    cp_B_half(g_w1h, 0, sb + OFF_B, tid);
    CP_COMMIT();
    load_A_fp16(x, row0, Aa, tid);
    if (tid < 256) { als[tid] = al1[tid]; ars[tid] = ar1[tid]; }

#pragma unroll 1
    for (int ct = 0; ct < 4; ++ct) {
        const int col0 = ct * 64;
        CP_WAIT(0);
        __syncthreads();

        float c[4][4];
#pragma unroll
        for (int g = 0; g < 4; ++g)
#pragma unroll
            for (int q = 0; q < 4; ++q) c[g][q] = 0.f;
        mma_krange<4>(sb, m0, n0, 0, 16, c);

        __syncthreads();
        if (ct < 3) {
            cp_B_half(g_w1h, col0 + 64, sb + OFF_B, tid);
            CP_COMMIT();
        }

        const int r0 = row0 + m0 + (lane >> 2);
        const int cbl = n0 + 2 * (lane & 3);
        float pel0 = 0.f, per0 = 0.f, pel8 = 0.f, per8 = 0.f;
#pragma unroll
        for (int g = 0; g < 4; ++g) {
            float a0 = als[col0 + cbl + g * 8], a1 = als[col0 + cbl + g * 8 + 1];
            float b0 = ars[col0 + cbl + g * 8], b1 = ars[col0 + cbl + g * 8 + 1];
            pel0 += c[g][0] * a0 + c[g][1] * a1;
            per0 += c[g][0] * b0 + c[g][1] * b1;
            pel8 += c[g][2] * a0 + c[g][3] * a1;
            per8 += c[g][2] * b0 + c[g][3] * b1;
            if (r0 < NN)
                *reinterpret_cast<__half2*>(g_fs1 + (size_t)r0 * 256 + col0 + cbl + g * 8) =
                    __floats2half2_rn(c[g][0], c[g][1]);
            if (r0 + 8 < NN)
                *reinterpret_cast<__half2*>(g_fs1 + (size_t)(r0 + 8) * 256 + col0 + cbl + g * 8) =
                    __floats2half2_rn(c[g][2], c[g][3]);
        }
        pel0 += __shfl_xor_sync(0xffffffffu, pel0, 1); pel0 += __shfl_xor_sync(0xffffffffu, pel0, 2);
        per0 += __shfl_xor_sync(0xffffffffu, per0, 1); per0 += __shfl_xor_sync(0xffffffffu, per0, 2);
        pel8 += __shfl_xor_sync(0xffffffffu, pel8, 1); pel8 += __shfl_xor_sync(0xffffffffu, pel8, 2);
        per8 += __shfl_xor_sync(0xffffffffu, per8, 1); per8 += __shfl_xor_sync(0xffffffffu, per8, 2);
        if ((lane & 3) == 0) {
            int rr = m0 + (lane >> 2);
            elp[wn][rr] = pel0; elp[wn][rr + 8] = pel8;
            erp[wn][rr] = per0; erp[wn][rr + 8] = per8;
        }
        __syncthreads();
        if (tid < 128) {
            int row = row0 + tid;
            if (row < NN) {
                g_el1[row * 4 + ct] = elp[0][tid] + elp[1][tid];
                g_er1[row * 4 + ct] = erp[0][tid] + erp[1][tid];
            }
        }
    }
}

// ================= GEMM2 (h2 @ W2) + el2/er2; N-tile 48, 2-stage K pipeline =============
__global__ void __launch_bounds__(512, 2) gemm2_mma_kernel(const float* __restrict__ al2,
                                                           const float* __restrict__ ar2)
{
    extern __shared__ __align__(16) char dsm[];
    __shared__ float als[48], ars[48];
    __shared__ float elp[2][128], erp[2][128];

    const uint32_t sb = smem_to_u32(dsm);
    const int tid  = threadIdx.x;
    const int lane = tid & 31;
    const int wid  = tid >> 5;
    const int wm = wid >> 1, wn = wid & 1;
    const int m0 = wm * 16, n0 = wn * 24;     // warp n-tile = 24 (3 groups)
    const int row0 = blockIdx.x * 128;

    cp_A_half_chunk(g_h2, row0, sb + OFF_A, tid, 0);
    cp_B48_chunk(g_w2h, sb + OFF_B, tid, 0);
    CP_COMMIT();
    cp_A_half_chunk(g_h2, row0, sb + OFF_A, tid, 1);
    cp_B48_chunk(g_w2h, sb + OFF_B, tid, 1);
    CP_COMMIT();
    if (tid < 48) {
        als[tid] = (tid < C2) ? al2[tid] : 0.f;
        ars[tid] = (tid < C2) ? ar2[tid] : 0.f;
    }

    float c[3][4];
#pragma unroll
    for (int g = 0; g < 3; ++g)
#pragma unroll
        for (int q = 0; q < 4; ++q) c[g][q] = 0.f;

    CP_WAIT(1);
    __syncthreads();
    mma_krange<3>(sb, m0, n0, 0, 8, c);
    CP_WAIT(0);
    __syncthreads();
    mma_krange<3>(sb, m0, n0, 8, 16, c);

    const int r0 = row0 + m0 + (lane >> 2);
    const int cbl = n0 + 2 * (lane & 3);
    float pel0 = 0.f, per0 = 0.f, pel8 = 0.f, per8 = 0.f;
#pragma unroll
    for (int g = 0; g < 3; ++g) {
        int cc = cbl + g * 8;
        float a0 = als[cc], a1 = als[cc + 1];
        float b0 = ars[cc], b1 = ars[cc + 1];
        pel0 += c[g][0] * a0 + c[g][1] * a1;
        per0 += c[g][0] * b0 + c[g][1] * b1;
        pel8 += c[g][2] * a0 + c[g][3] * a1;
        per8 += c[g][2] * b0 + c[g][3] * b1;
        if (r0 < NN)
            *reinterpret_cast<__half2*>(g_fs2h + (size_t)r0 * 64 + cc) =
                __floats2half2_rn(c[g][0], c[g][1]);
        if (r0 + 8 < NN)
            *reinterpret_cast<__half2*>(g_fs2h + (size_t)(r0 + 8) * 64 + cc) =
                __floats2half2_rn(c[g][2], c[g][3]);
    }
    pel0 += __shfl_xor_sync(0xffffffffu, pel0, 1); pel0 += __shfl_xor_sync(0xffffffffu, pel0, 2);
    per0 += __shfl_xor_sync(0xffffffffu, per0, 1); per0 += __shfl_xor_sync(0xffffffffu, per0, 2);
    pel8 += __shfl_xor_sync(0xffffffffu, pel8, 1); pel8 += __shfl_xor_sync(0xffffffffu, pel8, 2);
    per8 += __shfl_xor_sync(0xffffffffu, per8, 1); per8 += __shfl_xor_sync(0xffffffffu, per8, 2);
    if ((lane & 3) == 0) {
        int rr = m0 + (lane >> 2);
        elp[wn][rr] = pel0; elp[wn][rr + 8] = pel8;
        erp[wn][rr] = per0; erp[wn][rr + 8] = per8;
    }
    __syncthreads();
    if (tid < 128) {
        int row = row0 + tid;
        if (row < NN) {
            g_el2[row] = elp[0][tid] + elp[1][tid];
            g_er2[row] = erp[0][tid] + erp[1][tid];
        }
    }
}

// ---------------- layer-1 aggregation: WARP per node, software-pipelined gather (R13) ----
__global__ void __launch_bounds__(128, 8) agg1_kernel(const int* __restrict__ src,
                                                      const float* __restrict__ b1)
{
    __shared__ __half2 smwh[4][32][4];
    __shared__ int     smsrc[4][32];

    const int w    = threadIdx.x >> 5;
    const int lane = threadIdx.x & 31;
    const int n    = blockIdx.x * 4 + w;
    const int s = g_rowptr[n];
    const int e = g_rowptr[n + 1];
    const float4 er = *reinterpret_cast<const float4*>(g_er1 + n * 4);

    const int h = lane >> 3;
    float2 acc2[4];
#pragma unroll
    for (int q = 0; q < 4; ++q) acc2[q] = make_float2(0.f, 0.f);
    float den = 0.f;

    for (int base = s; base < e; base += 32) {
        int cnt = min(32, e - base);
        float4 wv = make_float4(0.f, 0.f, 0.f, 0.f);
        int sj = 0;
        if (lane < cnt) {
            sj = src[base + lane];
            float4 el = *reinterpret_cast<const float4*>(g_el1 + sj * 4);
            float v;
            v = el.x + er.x; v = v > 0.f ? v : 0.2f * v; wv.x = __expf(v);
            v = el.y + er.y; v = v > 0.f ? v : 0.2f * v; wv.y = __expf(v);
            v = el.z + er.z; v = v > 0.f ? v : 0.2f * v; wv.z = __expf(v);
            v = el.w + er.w; v = v > 0.f ? v : 0.2f * v; wv.w = __expf(v);
        }
        smsrc[w][lane] = sj;
        __half2 wh0 = __float2half2_rn(wv.x);
        __half2 wh1 = __float2half2_rn(wv.y);
        __half2 wh2 = __float2half2_rn(wv.z);
        __half2 wh3 = __float2half2_rn(wv.w);
        uint4 packed;
        packed.x = *reinterpret_cast<uint32_t*>(&wh0);
        packed.y = *reinterpret_cast<uint32_t*>(&wh1);
        packed.z = *reinterpret_cast<uint32_t*>(&wh2);
        packed.w = *reinterpret_cast<uint32_t*>(&wh3);
        *reinterpret_cast<uint4*>(&smwh[w][lane][0]) = packed;
        __syncwarp();

        const int cnt4 = (cnt + 3) & ~3;
        uint4   fc[4];
        __half2 wc[4];
#pragma unroll
        for (int t = 0; t < 4; ++t) {
            wc[t] = smwh[w][t][h];
            fc[t] = *reinterpret_cast<const uint4*>(
                g_fs1 + (size_t)smsrc[w][t] * 256 + lane * 8);
        }
        int j0 = 0;
#pragma unroll 1
        for (; j0 + 4 < cnt4; j0 += 4) {
            uint4   fn[4];
            __half2 wn[4];
#pragma unroll
            for (int t = 0; t < 4; ++t) {
                wn[t] = smwh[w][j0 + 4 + t][h];
                fn[t] = *reinterpret_cast<const uint4*>(
                    g_fs1 + (size_t)smsrc[w][j0 + 4 + t] * 256 + lane * 8);
            }
            __half2 hacc[4];
            {
                const __half2* hp = reinterpret_cast<const __half2*>(&fc[0]);
                den += __low2float(wc[0]);
#pragma unroll
                for (int q = 0; q < 4; ++q) hacc[q] = __hmul2(wc[0], hp[q]);
            }
#pragma unroll
            for (int t = 1; t < 4; ++t) {
                const __half2* hp = reinterpret_cast<const __half2*>(&fc[t]);
                den += __low2float(wc[t]);
#pragma unroll
                for (int q = 0; q < 4; ++q) hacc[q] = __hfma2(wc[t], hp[q], hacc[q]);
            }
#pragma unroll
            for (int q = 0; q < 4; ++q) {
                float2 fa = __half22float2(hacc[q]);
                acc2[q].x += fa.x; acc2[q].y += fa.y;
            }
#pragma unroll
            for (int t = 0; t < 4; ++t) { fc[t] = fn[t]; wc[t] = wn[t]; }
        }
        {
            __half2 hacc[4];
            {
                const __half2* hp = reinterpret_cast<const __half2*>(&fc[0]);
                den += __low2float(wc[0]);
#pragma unroll
                for (int q = 0; q < 4; ++q) hacc[q] = __hmul2(wc[0], hp[q]);
            }
#pragma unroll
            for (int t = 1; t < 4; ++t) {
                const __half2* hp = reinterpret_cast<const __half2*>(&fc[t]);
                den += __low2float(wc[t]);
#pragma unroll
                for (int q = 0; q < 4; ++q) hacc[q] = __hfma2(wc[t], hp[q], hacc[q]);
            }
#pragma unroll
            for (int q = 0; q < 4; ++q) {
                float2 fa = __half22float2(hacc[q]);
                acc2[q].x += fa.x; acc2[q].y += fa.y;
            }
        }
        __syncwarp();
    }

    float rden = (e > s) ? 1.f / den : 0.f;
    float4 bb0 = *reinterpret_cast<const float4*>(b1 + lane * 8);
    float4 bb1 = *reinterpret_cast<const float4*>(b1 + lane * 8 + 4);
    __half2 o[4];
    o[0] = __floats2half2_rn(fmaxf(acc2[0].x * rden + bb0.x, 0.f), fmaxf(acc2[0].y * rden + bb0.y, 0.f));
    o[1] = __floats2half2_rn(fmaxf(acc2[1].x * rden + bb0.z, 0.f), fmaxf(acc2[1].y * rden + bb0.w, 0.f));
    o[2] = __floats2half2_rn(fmaxf(acc2[2].x * rden + bb1.x, 0.f), fmaxf(acc2[2].y * rden + bb1.y, 0.f));
    o[3] = __floats2half2_rn(fmaxf(acc2[3].x * rden + bb1.z, 0.f), fmaxf(acc2[3].y * rden + bb1.w, 0.f));
    *reinterpret_cast<uint4*>(g_h2 + (size_t)n * 256 + lane * 8) = *reinterpret_cast<uint4*>(o);
}

// ---------------- layer-2 aggregation: WARP per node, software-pipelined gather (R13) ----
__global__ void __launch_bounds__(128, 12) agg2_kernel(const int* __restrict__ src,
                                                       const float* __restrict__ b2,
                                                       float* __restrict__ out)
{
    __shared__ __half2 smwh[4][32];
    __shared__ int     smsrc[4][32];

    const int w    = threadIdx.x >> 5;
    const int lane = threadIdx.x & 31;
    const int n    = blockIdx.x * 4 + w;
    const int s = g_rowptr[n];
    const int e = g_rowptr[n + 1];
    const float ern = g_er2[n];

    float2 acc = make_float2(0.f, 0.f);
    float den = 0.f;
    for (int base = s; base < e; base += 32) {
        int cnt = min(32, e - base);
        float wv = 0.f; int sj = 0;
        if (lane < cnt) {
            sj = src[base + lane];
            float v = g_el2[sj] + ern;
            v = v > 0.f ? v : 0.2f * v;
            wv = __expf(v);
        }
        smsrc[w][lane] = sj;
        smwh[w][lane] = __float2half2_rn(wv);
        __syncwarp();

        const int cnt4 = (cnt + 3) & ~3;
        __half2 fc[4], wc[4];
#pragma unroll
        for (int t = 0; t < 4; ++t) {
            wc[t] = smwh[w][t];
            fc[t] = *reinterpret_cast<const __half2*>(
                g_fs2h + (size_t)smsrc[w][t] * 64 + lane * 2);
        }
        int j0 = 0;
#pragma unroll 1
        for (; j0 + 4 < cnt4; j0 += 4) {
            __half2 fn[4], wn[4];
#pragma unroll
            for (int t = 0; t < 4; ++t) {
                wn[t] = smwh[w][j0 + 4 + t];
                fn[t] = *reinterpret_cast<const __half2*>(
                    g_fs2h + (size_t)smsrc[w][j0 + 4 + t] * 64 + lane * 2);
            }
            __half2 hacc = __hmul2(wc[0], fc[0]);
            den += __low2float(wc[0]);
#pragma unroll
            for (int t = 1; t < 4; ++t) {
                den += __low2float(wc[t]);
                hacc = __hfma2(wc[t], fc[t], hacc);
            }
            float2 fa = __half22float2(hacc);
            acc.x += fa.x; acc.y += fa.y;
#pragma unroll
            for (int t = 0; t < 4; ++t) { fc[t] = fn[t]; wc[t] = wn[t]; }
        }
        {
            __half2 hacc = __hmul2(wc[0], fc[0]);
            den += __low2float(wc[0]);
#pragma unroll
            for (int t = 1; t < 4; ++t) {
                den += __low2float(wc[t]);
                hacc = __hfma2(wc[t], fc[t], hacc);
            }
            float2 fa = __half22float2(hacc);
            acc.x += fa.x; acc.y += fa.y;
        }
        __syncwarp();
    }

    float rden = (e > s) ? 1.f / den : 0.f;
    float* orow = out + (size_t)n * C2;
    int cc = lane * 2;
    if (cc < C2)     orow[cc]     = acc.x * rden + b2[cc];
    if (cc + 1 < C2) orow[cc + 1] = acc.y * rden + b2[cc + 1];
}

// ---------------- launch ----------------
extern "C" void kernel_launch(void* const* d_in, const int* in_sizes, int n_in,
                              void* d_out, int out_size)
{
    const float* x   = (const float*)d_in[0];
    const float* W1  = (const float*)d_in[1];
    const float* al1 = (const float*)d_in[2];
    const float* ar1 = (const float*)d_in[3];
    const float* b1  = (const float*)d_in[4];
    const float* W2  = (const float*)d_in[5];
    const float* al2 = (const float*)d_in[6];
    const float* ar2 = (const float*)d_in[7];
    const float* b2  = (const float*)d_in[8];
    const int*   src = (const int*)d_in[9];
    const int*   dst = (const int*)d_in[10];
    float* out = (float*)d_out;

    (void)in_sizes; (void)n_in; (void)out_size;

    cudaFuncSetAttribute(gemm1_mma_kernel,
                         cudaFuncAttributeMaxDynamicSharedMemorySize, GEMM_SMEM);
    cudaFuncSetAttribute(gemm2_mma_kernel,
                         cudaFuncAttributeMaxDynamicSharedMemorySize, GEMM2_SMEM);

    prep_kernel<<<20 + PREP_EDGE_BLOCKS, 256>>>(W1, W2, dst);

    // Layer 1
    gemm1_mma_kernel<<<NN_PAD / 128, 512, GEMM_SMEM>>>(x, al1, ar1);
    agg1_kernel<<<NN / 4, 128>>>(src, b1);

    // Layer 2
    gemm2_mma_kernel<<<NN_PAD / 128, 512, GEMM2_SMEM>>>(al2, ar2);
    agg2_kernel<<<NN / 4, 128>>>(src, b2, out);
}